// round 2
// baseline (speedup 1.0000x reference)
#include <cuda_runtime.h>
#include <math.h>
#include <float.h>

// Problem constants
#define NROWS 32768
#define KC    8192
#define DIM   512

#define DECAYF 0.99f
#define OMDF   0.01f      // 1 - decay
#define EPSF   1e-5f

// ---- scratch (device globals: no allocation allowed) ----
__device__ float g_enorm2[KC];
__device__ int   g_idx[NROWS];
__device__ float g_counts[KC];
__device__ float g_dw[KC * DIM];
__device__ float g_cs_pre[KC];
__device__ float g_loss_sum;
__device__ float g_n_sum;
__device__ float g_plogp_sum;

// ---- output layout (concatenated, reference tuple order) ----
// quantized_st [N,D], loss [1], perplexity [1], new_embedding [K,D], new_cs [K], new_w [K,D]
// NOTE: O_EMB/O_CS/O_W are == 2 (mod 4) floats -> only 8-byte aligned. Use float2 there.
#define O_Q    0
#define O_LOSS (NROWS * DIM)
#define O_PERP (O_LOSS + 1)
#define O_EMB  (O_PERP + 1)
#define O_CS   (O_EMB + KC * DIM)
#define O_W    (O_CS + KC)

// ============================================================
// K0: zero scratch accumulators
// ============================================================
__global__ __launch_bounds__(256) void k_init() {
    int gid = blockIdx.x * blockDim.x + threadIdx.x;
    int stride = gridDim.x * blockDim.x;
    for (int i = gid; i < KC * DIM; i += stride) g_dw[i] = 0.0f;
    if (gid < KC) g_counts[gid] = 0.0f;
    if (gid == 0) { g_loss_sum = 0.0f; g_n_sum = 0.0f; g_plogp_sum = 0.0f; }
}

// ============================================================
// K1: ||e_k||^2  (one warp per code row)
// ============================================================
__global__ __launch_bounds__(256) void k_enorm2(const float* __restrict__ E) {
    int warp = (blockIdx.x * blockDim.x + threadIdx.x) >> 5;
    int lane = threadIdx.x & 31;
    if (warp >= KC) return;
    const float* row = E + (size_t)warp * DIM;
    float s = 0.0f;
    #pragma unroll
    for (int d = lane * 4; d < DIM; d += 32 * 4) {
        float4 v = *(const float4*)(row + d);
        s = fmaf(v.x, v.x, s); s = fmaf(v.y, v.y, s);
        s = fmaf(v.z, v.z, s); s = fmaf(v.w, v.w, s);
    }
    #pragma unroll
    for (int o = 16; o; o >>= 1) s += __shfl_xor_sync(0xffffffffu, s, o);
    if (lane == 0) g_enorm2[warp] = s;
}

// ============================================================
// K2: fused distance-GEMM + running argmin
// 128 rows/CTA x all 8192 codes; 8x8 microtile; BK=32.
// s_k = ||e_k||^2 - 2 x.e_k  (||x||^2 constant per row, dropped)
// ============================================================
#define BM 128
#define BN 128
#define BK 32
#define TM 8
#define TN 8

__global__ __launch_bounds__(256, 2) void k_argmin(const float* __restrict__ X,
                                                   const float* __restrict__ E) {
    __shared__ float Xs[BK][BM + 4];   // [k][row], pad 4 keeps float4 alignment
    __shared__ float Es[BK][BN + 4];

    const int tid = threadIdx.x;
    const int tr  = tid >> 4;          // 0..15 : row group
    const int tc  = tid & 15;          // 0..15 : col group
    const int lrow = tid >> 3;         // 0..31 : staging row
    const int lk   = (tid & 7) * 4;    // 0..28 : staging k offset

    const int block_row = blockIdx.x * BM;
    const float* Xblk = X + (size_t)block_row * DIM;

    float minv[TM];
    int   mini[TM];
    #pragma unroll
    for (int i = 0; i < TM; ++i) { minv[i] = FLT_MAX; mini[i] = 0x7fffffff; }

    #pragma unroll 1
    for (int t = 0; t < KC / BN; ++t) {
        const float* Eblk = E + (size_t)(t * BN) * DIM;
        float acc[TM][TN];
        #pragma unroll
        for (int i = 0; i < TM; ++i)
            #pragma unroll
            for (int j = 0; j < TN; ++j) acc[i][j] = 0.0f;

        #pragma unroll 1
        for (int d0 = 0; d0 < DIM; d0 += BK) {
            #pragma unroll
            for (int r = 0; r < 4; ++r) {
                int row = lrow + r * 32;
                float4 xv = *(const float4*)(Xblk + (size_t)row * DIM + d0 + lk);
                Xs[lk + 0][row] = xv.x; Xs[lk + 1][row] = xv.y;
                Xs[lk + 2][row] = xv.z; Xs[lk + 3][row] = xv.w;
                float4 ev = *(const float4*)(Eblk + (size_t)row * DIM + d0 + lk);
                Es[lk + 0][row] = ev.x; Es[lk + 1][row] = ev.y;
                Es[lk + 2][row] = ev.z; Es[lk + 3][row] = ev.w;
            }
            __syncthreads();

            #pragma unroll
            for (int kk = 0; kk < BK; ++kk) {
                float xv[TM], ev[TN];
                *(float4*)&xv[0] = *(const float4*)&Xs[kk][tr * TM];
                *(float4*)&xv[4] = *(const float4*)&Xs[kk][tr * TM + 4];
                *(float4*)&ev[0] = *(const float4*)&Es[kk][tc * TN];
                *(float4*)&ev[4] = *(const float4*)&Es[kk][tc * TN + 4];
                #pragma unroll
                for (int i = 0; i < TM; ++i)
                    #pragma unroll
                    for (int j = 0; j < TN; ++j)
                        acc[i][j] = fmaf(xv[i], ev[j], acc[i][j]);
            }
            __syncthreads();
        }

        // fold this tile into running argmin (col ascending -> first-min tie-break)
        #pragma unroll
        for (int j = 0; j < TN; ++j) {
            int col = t * BN + tc * TN + j;
            float en = __ldg(&g_enorm2[col]);
            #pragma unroll
            for (int i = 0; i < TM; ++i) {
                float s = fmaf(-2.0f, acc[i][j], en);
                if (s < minv[i]) { minv[i] = s; mini[i] = col; }
            }
        }
    }

    // cross-thread reduction: 16 candidates per row -> 1. Reuse smem.
    float* rv = (float*)Xs;   // 128*16 floats = 8KB (< 16.9KB)
    int*   ri = (int*)Es;
    #pragma unroll
    for (int i = 0; i < TM; ++i) {
        rv[(tr * TM + i) * 16 + tc] = minv[i];
        ri[(tr * TM + i) * 16 + tc] = mini[i];
    }
    __syncthreads();
    if (tid < BM) {
        float best = FLT_MAX; int bi = 0x7fffffff;
        #pragma unroll
        for (int c = 0; c < 16; ++c) {
            float v = rv[tid * 16 + c];
            int   id = ri[tid * 16 + c];
            if (v < best || (v == best && id < bi)) { best = v; bi = id; }
        }
        g_idx[block_row + tid] = bi;
    }
}

// ============================================================
// K3: gather quantized, loss partial, counts, dw scatter-add.
// One block per input row, 128 threads (1 float4 each).
// ============================================================
__global__ __launch_bounds__(128) void k_gather(const float* __restrict__ X,
                                                const float* __restrict__ E,
                                                float* __restrict__ out) {
    __shared__ float warp_sums[4];
    int row = blockIdx.x;
    int idx = g_idx[row];
    if (threadIdx.x == 0) atomicAdd(&g_counts[idx], 1.0f);

    const float* xr = X + (size_t)row * DIM;
    const float* er = E + (size_t)idx * DIM;
    float* dwr = g_dw + (size_t)idx * DIM;
    float* qr  = out + O_Q + (size_t)row * DIM;

    int d = threadIdx.x * 4;
    float4 q = *(const float4*)(er + d);
    float4 x = *(const float4*)(xr + d);
    *(float4*)(qr + d) = q;
    atomicAdd(dwr + d + 0, x.x);
    atomicAdd(dwr + d + 1, x.y);
    atomicAdd(dwr + d + 2, x.z);
    atomicAdd(dwr + d + 3, x.w);

    float dx = q.x - x.x, dy = q.y - x.y, dz = q.z - x.z, dw = q.w - x.w;
    float ls = dx * dx + dy * dy + dz * dz + dw * dw;
    #pragma unroll
    for (int o = 16; o; o >>= 1) ls += __shfl_xor_sync(0xffffffffu, ls, o);
    int lane = threadIdx.x & 31, warp = threadIdx.x >> 5;
    if (lane == 0) warp_sums[warp] = ls;
    __syncthreads();
    if (threadIdx.x == 0) {
        float s = warp_sums[0] + warp_sums[1] + warp_sums[2] + warp_sums[3];
        atomicAdd(&g_loss_sum, s);
    }
}

// ============================================================
// K4a: cs_pre = cs*decay + (1-decay)*counts; accumulate n and p*log(p)
// ============================================================
__global__ __launch_bounds__(256) void k_stats1(const float* __restrict__ cs_in) {
    __shared__ float sn[8], sp[8];
    int k = blockIdx.x * 256 + threadIdx.x;
    float cnt = g_counts[k];
    float pre = fmaf(cs_in[k], DECAYF, OMDF * cnt);
    g_cs_pre[k] = pre;
    float p = cnt * (1.0f / (float)NROWS);
    float pl = p * logf(p + 1e-10f);
    float ns = pre, ps = pl;
    #pragma unroll
    for (int o = 16; o; o >>= 1) {
        ns += __shfl_xor_sync(0xffffffffu, ns, o);
        ps += __shfl_xor_sync(0xffffffffu, ps, o);
    }
    int lane = threadIdx.x & 31, warp = threadIdx.x >> 5;
    if (lane == 0) { sn[warp] = ns; sp[warp] = ps; }
    __syncthreads();
    if (threadIdx.x == 0) {
        float a = 0.0f, b = 0.0f;
        #pragma unroll
        for (int w = 0; w < 8; ++w) { a += sn[w]; b += sp[w]; }
        atomicAdd(&g_n_sum, a);
        atomicAdd(&g_plogp_sum, b);
    }
}

// ============================================================
// K4b: finalize new_cs + scalars
// ============================================================
__global__ __launch_bounds__(256) void k_stats2(float* __restrict__ out) {
    int k = blockIdx.x * 256 + threadIdx.x;
    float n = g_n_sum;
    float ncs = (g_cs_pre[k] + EPSF) / (n + (float)KC * EPSF) * n;
    out[O_CS + k] = ncs;
    if (blockIdx.x == 0 && threadIdx.x == 0) {
        out[O_LOSS] = 0.25f * (g_loss_sum / (float)(NROWS * DIM));
        out[O_PERP] = expf(-g_plogp_sum);
    }
}

// ============================================================
// K5: new_w = ema_w*decay + (1-decay)*dw ;  new_emb = new_w / new_cs[k]
// Output regions O_W / O_EMB are only 8-byte aligned -> float2 stores.
// ============================================================
__global__ __launch_bounds__(256) void k_final(const float* __restrict__ ema_w,
                                               float* __restrict__ out) {
    const float* ncs = out + O_CS;
    int i = blockIdx.x * blockDim.x + threadIdx.x;
    int total = KC * DIM / 4;
    int stride = gridDim.x * blockDim.x;
    for (; i < total; i += stride) {
        int e = i * 4;
        int k = e >> 9;   // /DIM
        float4 w  = *(const float4*)(ema_w + e);
        float4 dv = *(const float4*)(g_dw + e);
        float4 nw;
        nw.x = fmaf(w.x, DECAYF, OMDF * dv.x);
        nw.y = fmaf(w.y, DECAYF, OMDF * dv.y);
        nw.z = fmaf(w.z, DECAYF, OMDF * dv.z);
        nw.w = fmaf(w.w, DECAYF, OMDF * dv.w);
        *(float2*)(out + O_W + e)     = make_float2(nw.x, nw.y);
        *(float2*)(out + O_W + e + 2) = make_float2(nw.z, nw.w);
        float c = ncs[k];
        float inv = 1.0f / c;
        *(float2*)(out + O_EMB + e)     = make_float2(nw.x * inv, nw.y * inv);
        *(float2*)(out + O_EMB + e + 2) = make_float2(nw.z * inv, nw.w * inv);
    }
}

// ============================================================
extern "C" void kernel_launch(void* const* d_in, const int* in_sizes, int n_in,
                              void* d_out, int out_size) {
    const float* X     = (const float*)d_in[0];  // inputs [32768,512]
    const float* E     = (const float*)d_in[1];  // embedding [8192,512]
    const float* cs    = (const float*)d_in[2];  // ema_cluster_size [8192]
    const float* ema_w = (const float*)d_in[3];  // ema_w [8192,512]
    float* out = (float*)d_out;

    k_init  <<<4096, 256>>>();
    k_enorm2<<<KC / 8, 256>>>(E);
    k_argmin<<<NROWS / BM, 256>>>(X, E);
    k_gather<<<NROWS, 128>>>(X, E, out);
    k_stats1<<<KC / 256, 256>>>(cs);
    k_stats2<<<KC / 256, 256>>>(out);
    k_final <<<2048, 256>>>(ema_w, out);
}

// round 4
// speedup vs baseline: 2.2893x; 2.2893x over previous
#include <cuda_runtime.h>
#include <cuda_bf16.h>
#include <math.h>
#include <float.h>
#include <stdint.h>

// Problem constants
#define NROWS 32768
#define KC    8192
#define DIM   512

#define DECAYF 0.99f
#define OMDF   0.01f
#define EPSF   1e-5f

// ============================================================
// scratch (device globals)
// ============================================================
__device__ float g_enorm2[KC];
__device__ int   g_idx[NROWS];
__device__ float g_counts[KC];
__device__ float g_dw[KC * DIM];
__device__ float g_cs_pre[KC];
__device__ float g_loss_sum;
__device__ float g_n_sum;
__device__ float g_plogp_sum;

// bf16 split operands, plain row-major [rows][512]
__device__ __nv_bfloat16 g_xhi[NROWS * DIM];
__device__ __nv_bfloat16 g_xlo[NROWS * DIM];
__device__ __nv_bfloat16 g_ehi[KC * DIM];
__device__ __nv_bfloat16 g_elo[KC * DIM];

// ---- output layout (O_EMB/O_W only 8-byte aligned -> float2 there) ----
#define O_Q    0
#define O_LOSS (NROWS * DIM)
#define O_PERP (O_LOSS + 1)
#define O_EMB  (O_PERP + 1)
#define O_CS   (O_EMB + KC * DIM)
#define O_W    (O_CS + KC)

// ============================================================
// small PTX helpers (all baseline compute_100: sm_80+ features)
// ============================================================
__device__ __forceinline__ uint32_t smem_u32(const void* p) {
    uint32_t a;
    asm("{ .reg .u64 t; cvta.to.shared.u64 t, %1; cvt.u32.u64 %0, t; }" : "=r"(a) : "l"(p));
    return a;
}
__device__ __forceinline__ void cp16(uint32_t dst, const void* src) {
    asm volatile("cp.async.cg.shared.global [%0], [%1], 16;" :: "r"(dst), "l"(src) : "memory");
}
__device__ __forceinline__ void cp_commit() { asm volatile("cp.async.commit_group;" ::: "memory"); }
__device__ __forceinline__ void cp_wait0()  { asm volatile("cp.async.wait_group 0;" ::: "memory"); }

__device__ __forceinline__ void ldsm4(uint32_t* r, uint32_t addr) {
    asm volatile("ldmatrix.sync.aligned.m8n8.x4.shared.b16 {%0,%1,%2,%3}, [%4];"
        : "=r"(r[0]), "=r"(r[1]), "=r"(r[2]), "=r"(r[3]) : "r"(addr));
}
__device__ __forceinline__ void mma16816(float* c, const uint32_t* a, const uint32_t* b) {
    asm volatile(
        "mma.sync.aligned.m16n8k16.row.col.f32.bf16.bf16.f32 "
        "{%0,%1,%2,%3}, {%4,%5,%6,%7}, {%8,%9}, {%0,%1,%2,%3};"
        : "+f"(c[0]), "+f"(c[1]), "+f"(c[2]), "+f"(c[3])
        : "r"(a[0]), "r"(a[1]), "r"(a[2]), "r"(a[3]), "r"(b[0]), "r"(b[1]));
}

// ============================================================
// K0: zero scratch accumulators
// ============================================================
__global__ __launch_bounds__(256) void k_init() {
    int gid = blockIdx.x * blockDim.x + threadIdx.x;
    int stride = gridDim.x * blockDim.x;
    for (int i = gid; i < KC * DIM; i += stride) g_dw[i] = 0.0f;
    if (gid < KC) g_counts[gid] = 0.0f;
    if (gid == 0) { g_loss_sum = 0.0f; g_n_sum = 0.0f; g_plogp_sum = 0.0f; }
}

// ============================================================
// K1: split fp32 -> bf16 hi/lo (row-major)
// ============================================================
__device__ __forceinline__ void split4(float4 v, uint2& hi, uint2& lo) {
    __nv_bfloat16 h0 = __float2bfloat16_rn(v.x);
    __nv_bfloat16 h1 = __float2bfloat16_rn(v.y);
    __nv_bfloat16 h2 = __float2bfloat16_rn(v.z);
    __nv_bfloat16 h3 = __float2bfloat16_rn(v.w);
    __nv_bfloat16 l0 = __float2bfloat16_rn(v.x - __bfloat162float(h0));
    __nv_bfloat16 l1 = __float2bfloat16_rn(v.y - __bfloat162float(h1));
    __nv_bfloat16 l2 = __float2bfloat16_rn(v.z - __bfloat162float(h2));
    __nv_bfloat16 l3 = __float2bfloat16_rn(v.w - __bfloat162float(h3));
    hi.x = ((uint32_t)__bfloat16_as_ushort(h1) << 16) | __bfloat16_as_ushort(h0);
    hi.y = ((uint32_t)__bfloat16_as_ushort(h3) << 16) | __bfloat16_as_ushort(h2);
    lo.x = ((uint32_t)__bfloat16_as_ushort(l1) << 16) | __bfloat16_as_ushort(l0);
    lo.y = ((uint32_t)__bfloat16_as_ushort(l3) << 16) | __bfloat16_as_ushort(l2);
}

__global__ __launch_bounds__(256) void k_conv(const float* __restrict__ src,
                                              __nv_bfloat16* __restrict__ hi,
                                              __nv_bfloat16* __restrict__ lo,
                                              int n4) {
    int stride = gridDim.x * blockDim.x;
    for (int g = blockIdx.x * blockDim.x + threadIdx.x; g < n4; g += stride) {
        float4 v = *(const float4*)(src + (size_t)g * 4);
        uint2 h, l; split4(v, h, l);
        ((uint2*)hi)[g] = h;
        ((uint2*)lo)[g] = l;
    }
}

// ============================================================
// K2: ||e_k||^2 (fp32, one warp per code row)
// ============================================================
__global__ __launch_bounds__(256) void k_enorm2(const float* __restrict__ E) {
    int warp = (blockIdx.x * blockDim.x + threadIdx.x) >> 5;
    int lane = threadIdx.x & 31;
    if (warp >= KC) return;
    const float* row = E + (size_t)warp * DIM;
    float s = 0.0f;
    #pragma unroll
    for (int d = lane * 4; d < DIM; d += 32 * 4) {
        float4 v = *(const float4*)(row + d);
        s = fmaf(v.x, v.x, s); s = fmaf(v.y, v.y, s);
        s = fmaf(v.z, v.z, s); s = fmaf(v.w, v.w, s);
    }
    #pragma unroll
    for (int o = 16; o; o >>= 1) s += __shfl_xor_sync(0xffffffffu, s, o);
    if (lane == 0) g_enorm2[warp] = s;
}

// ============================================================
// K3: bf16 mma.sync distance GEMM + fused argmin
// CTA: 128 input rows; loop 64 n-tiles of 128 codes; BK=32, K=512.
// 3 split-products (hh, hl, lh) into fp32 accumulators.
// 8 warps as 2 (rows) x 4 (cols); warp tile 64x32; m16n8k16.
// smem: double-buffered 4 tiles (Ah,Al,Bh,Bl), 128 rows x 32 bf16,
// row stride 80B (pad) -> conflict-free ldmatrix. 2 x 40960 B.
// ============================================================
#define TILE_B   10240     // one operand tile: 128 * 80 bytes
#define BUF_B    40960     // 4 tiles
#define SMEM_MMA (2 * BUF_B)

__device__ __forceinline__ void stage_chunk(uint32_t sbuf, int mt, int t, int kc, int tid) {
    // 2048 x 16B segments; tile i>>1 of {Ah,Al,Bh,Bl}
    const char* gb[4] = { (const char*)g_xhi, (const char*)g_xlo,
                          (const char*)g_ehi, (const char*)g_elo };
    const int rb[4] = { mt * 128, mt * 128, t * 128, t * 128 };
    #pragma unroll
    for (int i = 0; i < 8; ++i) {
        const int tile = i >> 1;
        int r = ((i & 1) << 6) + (tid >> 2);
        int c = tid & 3;
        const char* src = gb[tile] + (size_t)(rb[tile] + r) * (DIM * 2) + kc * 64 + c * 16;
        cp16(sbuf + tile * TILE_B + r * 80 + c * 16, src);
    }
}

__global__ __launch_bounds__(256, 1) void k_argmin_mma() {
    extern __shared__ char smem[];
    const uint32_t sb = smem_u32(smem);
    const int tid = threadIdx.x;
    const int lane = tid & 31;
    const int wid = tid >> 5;
    const int wr = wid >> 2;           // 0..1 : 64-row band
    const int wc = wid & 3;            // 0..3 : 32-col band
    const int mt = blockIdx.x;

    // per-lane ldmatrix base offsets
    const uint32_t offA = (uint32_t)((wr * 64 + (lane & 15)) * 80 + ((lane >> 4) & 1) * 16);
    const uint32_t offB = (uint32_t)((wc * 32 + (lane & 7) + ((lane >> 4) & 1) * 8) * 80
                                     + ((lane >> 3) & 1) * 16);

    float minv[8];
    int   mini[8];
    #pragma unroll
    for (int i = 0; i < 8; ++i) { minv[i] = FLT_MAX; mini[i] = 0x7fffffff; }

    #pragma unroll 1
    for (int t = 0; t < KC / 128; ++t) {
        float acc[4][4][4];
        #pragma unroll
        for (int m = 0; m < 4; ++m)
            #pragma unroll
            for (int n = 0; n < 4; ++n)
                #pragma unroll
                for (int r = 0; r < 4; ++r) acc[m][n][r] = 0.0f;

        stage_chunk(sb, mt, t, 0, tid);
        cp_commit();

        #pragma unroll 1
        for (int kc = 0; kc < DIM / 32; ++kc) {
            cp_wait0();
            __syncthreads();
            if (kc + 1 < DIM / 32) {
                stage_chunk(sb + ((kc + 1) & 1) * BUF_B, mt, t, kc + 1, tid);
                cp_commit();
            }
            const uint32_t buf = sb + (kc & 1) * BUF_B;

            #pragma unroll
            for (int ks = 0; ks < 2; ++ks) {
                uint32_t aH[4][4], aL[4][4], bH[2][4], bL[2][4];
                #pragma unroll
                for (int m = 0; m < 4; ++m) {
                    uint32_t ad = buf + offA + m * (16 * 80) + ks * 32;
                    ldsm4(aH[m], ad);
                    ldsm4(aL[m], ad + TILE_B);
                }
                #pragma unroll
                for (int p = 0; p < 2; ++p) {
                    uint32_t bd = buf + 2 * TILE_B + offB + p * (16 * 80) + ks * 32;
                    ldsm4(bH[p], bd);
                    ldsm4(bL[p], bd + TILE_B);
                }
                #pragma unroll
                for (int m = 0; m < 4; ++m)
                    #pragma unroll
                    for (int n = 0; n < 4; ++n) {
                        const uint32_t* bh = &bH[n >> 1][(n & 1) * 2];
                        const uint32_t* bl = &bL[n >> 1][(n & 1) * 2];
                        mma16816(acc[m][n], aH[m], bh);
                        mma16816(acc[m][n], aH[m], bl);
                        mma16816(acc[m][n], aL[m], bh);
                    }
            }
            __syncthreads();   // all warps done with buf before restage
        }

        // fold tile distances into running argmin
        #pragma unroll
        for (int n = 0; n < 4; ++n) {
            const int colb = t * 128 + wc * 32 + n * 8 + 2 * (lane & 3);
            const float en0 = __ldg(&g_enorm2[colb]);
            const float en1 = __ldg(&g_enorm2[colb + 1]);
            #pragma unroll
            for (int m = 0; m < 4; ++m) {
                #pragma unroll
                for (int r = 0; r < 4; ++r) {
                    const float en = (r & 1) ? en1 : en0;
                    const int col = colb + (r & 1);
                    const int rs = m * 2 + (r >> 1);
                    float s = fmaf(-2.0f, acc[m][n][r], en);
                    if (s < minv[rs]) { minv[rs] = s; mini[rs] = col; }
                }
            }
        }
    }

    // cross-thread reduction: 16 candidates per row (4 col-warps x 4 lanes)
    __syncthreads();
    float* rv = (float*)smem;                 // 128*16 floats = 8KB
    int*   ri = (int*)(smem + 8192);
    #pragma unroll
    for (int m = 0; m < 4; ++m)
        #pragma unroll
        for (int h = 0; h < 2; ++h) {
            int row = wr * 64 + m * 16 + h * 8 + (lane >> 2);
            int slot = wc * 4 + (lane & 3);
            rv[row * 16 + slot] = minv[m * 2 + h];
            ri[row * 16 + slot] = mini[m * 2 + h];
        }
    __syncthreads();
    if (tid < 128) {
        float best = FLT_MAX; int bi = 0x7fffffff;
        #pragma unroll
        for (int c = 0; c < 16; ++c) {
            float v = rv[tid * 16 + c];
            int   id = ri[tid * 16 + c];
            if (v < best || (v == best && id < bi)) { best = v; bi = id; }
        }
        g_idx[mt * 128 + tid] = bi;
    }
}

// ============================================================
// K4: gather quantized, loss partial, counts, dw scatter-add
// ============================================================
__global__ __launch_bounds__(128) void k_gather(const float* __restrict__ X,
                                                const float* __restrict__ E,
                                                float* __restrict__ out) {
    __shared__ float warp_sums[4];
    int row = blockIdx.x;
    int idx = g_idx[row];
    if (threadIdx.x == 0) atomicAdd(&g_counts[idx], 1.0f);

    const float* xr = X + (size_t)row * DIM;
    const float* er = E + (size_t)idx * DIM;
    float* dwr = g_dw + (size_t)idx * DIM;
    float* qr  = out + O_Q + (size_t)row * DIM;

    int d = threadIdx.x * 4;
    float4 q = *(const float4*)(er + d);
    float4 x = *(const float4*)(xr + d);
    *(float4*)(qr + d) = q;
    atomicAdd(dwr + d + 0, x.x);
    atomicAdd(dwr + d + 1, x.y);
    atomicAdd(dwr + d + 2, x.z);
    atomicAdd(dwr + d + 3, x.w);

    float dx = q.x - x.x, dy = q.y - x.y, dz = q.z - x.z, dw = q.w - x.w;
    float ls = dx * dx + dy * dy + dz * dz + dw * dw;
    #pragma unroll
    for (int o = 16; o; o >>= 1) ls += __shfl_xor_sync(0xffffffffu, ls, o);
    int lane = threadIdx.x & 31, warp = threadIdx.x >> 5;
    if (lane == 0) warp_sums[warp] = ls;
    __syncthreads();
    if (threadIdx.x == 0) {
        float s = warp_sums[0] + warp_sums[1] + warp_sums[2] + warp_sums[3];
        atomicAdd(&g_loss_sum, s);
    }
}

// ============================================================
// K5a: EMA cluster-size pre + global sums
// ============================================================
__global__ __launch_bounds__(256) void k_stats1(const float* __restrict__ cs_in) {
    __shared__ float sn[8], sp[8];
    int k = blockIdx.x * 256 + threadIdx.x;
    float cnt = g_counts[k];
    float pre = fmaf(cs_in[k], DECAYF, OMDF * cnt);
    g_cs_pre[k] = pre;
    float p = cnt * (1.0f / (float)NROWS);
    float pl = p * logf(p + 1e-10f);
    float ns = pre, ps = pl;
    #pragma unroll
    for (int o = 16; o; o >>= 1) {
        ns += __shfl_xor_sync(0xffffffffu, ns, o);
        ps += __shfl_xor_sync(0xffffffffu, ps, o);
    }
    int lane = threadIdx.x & 31, warp = threadIdx.x >> 5;
    if (lane == 0) { sn[warp] = ns; sp[warp] = ps; }
    __syncthreads();
    if (threadIdx.x == 0) {
        float a = 0.0f, b = 0.0f;
        #pragma unroll
        for (int w = 0; w < 8; ++w) { a += sn[w]; b += sp[w]; }
        atomicAdd(&g_n_sum, a);
        atomicAdd(&g_plogp_sum, b);
    }
}

// ============================================================
// K5b: finalize new_cs + scalars
// ============================================================
__global__ __launch_bounds__(256) void k_stats2(float* __restrict__ out) {
    int k = blockIdx.x * 256 + threadIdx.x;
    float n = g_n_sum;
    float ncs = (g_cs_pre[k] + EPSF) / (n + (float)KC * EPSF) * n;
    out[O_CS + k] = ncs;
    if (blockIdx.x == 0 && threadIdx.x == 0) {
        out[O_LOSS] = 0.25f * (g_loss_sum / (float)(NROWS * DIM));
        out[O_PERP] = expf(-g_plogp_sum);
    }
}

// ============================================================
// K6: new_w + new_embedding (float2 stores: regions only 8B aligned)
// ============================================================
__global__ __launch_bounds__(256) void k_final(const float* __restrict__ ema_w,
                                               float* __restrict__ out) {
    const float* ncs = out + O_CS;
    int i = blockIdx.x * blockDim.x + threadIdx.x;
    int total = KC * DIM / 4;
    int stride = gridDim.x * blockDim.x;
    for (; i < total; i += stride) {
        int e = i * 4;
        int k = e >> 9;
        float4 w  = *(const float4*)(ema_w + e);
        float4 dv = *(const float4*)(g_dw + e);
        float4 nw;
        nw.x = fmaf(w.x, DECAYF, OMDF * dv.x);
        nw.y = fmaf(w.y, DECAYF, OMDF * dv.y);
        nw.z = fmaf(w.z, DECAYF, OMDF * dv.z);
        nw.w = fmaf(w.w, DECAYF, OMDF * dv.w);
        *(float2*)(out + O_W + e)     = make_float2(nw.x, nw.y);
        *(float2*)(out + O_W + e + 2) = make_float2(nw.z, nw.w);
        float inv = 1.0f / ncs[k];
        *(float2*)(out + O_EMB + e)     = make_float2(nw.x * inv, nw.y * inv);
        *(float2*)(out + O_EMB + e + 2) = make_float2(nw.z * inv, nw.w * inv);
    }
}

// ============================================================
extern "C" void kernel_launch(void* const* d_in, const int* in_sizes, int n_in,
                              void* d_out, int out_size) {
    const float* X     = (const float*)d_in[0];
    const float* E     = (const float*)d_in[1];
    const float* cs    = (const float*)d_in[2];
    const float* ema_w = (const float*)d_in[3];
    float* out = (float*)d_out;

    static int attr_set = 0;
    if (!attr_set) {
        cudaFuncSetAttribute(k_argmin_mma, cudaFuncAttributeMaxDynamicSharedMemorySize, SMEM_MMA);
        attr_set = 1;
    }

    __nv_bfloat16 *xhi, *xlo, *ehi, *elo;
    cudaGetSymbolAddress((void**)&xhi, g_xhi);
    cudaGetSymbolAddress((void**)&xlo, g_xlo);
    cudaGetSymbolAddress((void**)&ehi, g_ehi);
    cudaGetSymbolAddress((void**)&elo, g_elo);

    k_init  <<<4096, 256>>>();
    k_conv  <<<2048, 256>>>(X, xhi, xlo, NROWS * DIM / 4);
    k_conv  <<<1024, 256>>>(E, ehi, elo, KC * DIM / 4);
    k_enorm2<<<KC / 8, 256>>>(E);
    k_argmin_mma<<<NROWS / 128, 256, SMEM_MMA>>>();
    k_gather<<<NROWS, 128>>>(X, E, out);
    k_stats1<<<KC / 256, 256>>>(cs);
    k_stats2<<<KC / 256, 256>>>(out);
    k_final <<<2048, 256>>>(ema_w, out);
}

// round 5
// speedup vs baseline: 5.1706x; 2.2586x over previous
#include <cuda_runtime.h>
#include <cuda_bf16.h>
#include <math.h>
#include <float.h>
#include <stdint.h>

// Problem constants
#define NROWS 32768
#define KC    8192
#define DIM   512

#define DECAYF 0.99f
#define OMDF   0.01f
#define EPSF   1e-5f

#define NCAND 16          // candidates per row for exact re-rank

// ============================================================
// scratch (device globals)
// ============================================================
__device__ float g_enorm2[KC];
__device__ int   g_idx[NROWS];
__device__ int   g_cand[NROWS * NCAND];
__device__ float g_counts[KC];
__device__ float g_dw[KC * DIM];
__device__ float g_cs_pre[KC];
__device__ float g_loss_sum;
__device__ float g_n_sum;
__device__ float g_plogp_sum;

// bf16 hi operands, row-major [rows][512]
__device__ __nv_bfloat16 g_xhi[NROWS * DIM];
__device__ __nv_bfloat16 g_ehi[KC * DIM];

// ---- output layout (O_EMB/O_W only 8-byte aligned -> float2 there) ----
#define O_Q    0
#define O_LOSS (NROWS * DIM)
#define O_PERP (O_LOSS + 1)
#define O_EMB  (O_PERP + 1)
#define O_CS   (O_EMB + KC * DIM)
#define O_W    (O_CS + KC)

// ============================================================
// PTX helpers (baseline compute_100 = sm_80+ features only)
// ============================================================
__device__ __forceinline__ uint32_t smem_u32(const void* p) {
    uint32_t a;
    asm("{ .reg .u64 t; cvta.to.shared.u64 t, %1; cvt.u32.u64 %0, t; }" : "=r"(a) : "l"(p));
    return a;
}
__device__ __forceinline__ void cp16(uint32_t dst, const void* src) {
    asm volatile("cp.async.cg.shared.global [%0], [%1], 16;" :: "r"(dst), "l"(src) : "memory");
}
__device__ __forceinline__ void cp_commit() { asm volatile("cp.async.commit_group;" ::: "memory"); }
__device__ __forceinline__ void cp_wait0()  { asm volatile("cp.async.wait_group 0;" ::: "memory"); }

__device__ __forceinline__ void ldsm4(uint32_t* r, uint32_t addr) {
    asm volatile("ldmatrix.sync.aligned.m8n8.x4.shared.b16 {%0,%1,%2,%3}, [%4];"
        : "=r"(r[0]), "=r"(r[1]), "=r"(r[2]), "=r"(r[3]) : "r"(addr));
}
__device__ __forceinline__ void mma16816(float* c, const uint32_t* a, const uint32_t* b) {
    asm volatile(
        "mma.sync.aligned.m16n8k16.row.col.f32.bf16.bf16.f32 "
        "{%0,%1,%2,%3}, {%4,%5,%6,%7}, {%8,%9}, {%0,%1,%2,%3};"
        : "+f"(c[0]), "+f"(c[1]), "+f"(c[2]), "+f"(c[3])
        : "r"(a[0]), "r"(a[1]), "r"(a[2]), "r"(a[3]), "r"(b[0]), "r"(b[1]));
}

// ============================================================
// K0: zero scratch accumulators
// ============================================================
__global__ __launch_bounds__(256) void k_init() {
    int gid = blockIdx.x * blockDim.x + threadIdx.x;
    int stride = gridDim.x * blockDim.x;
    for (int i = gid; i < KC * DIM; i += stride) g_dw[i] = 0.0f;
    if (gid < KC) g_counts[gid] = 0.0f;
    if (gid == 0) { g_loss_sum = 0.0f; g_n_sum = 0.0f; g_plogp_sum = 0.0f; }
}

// ============================================================
// K1: fp32 -> bf16 (hi only), row-major
// ============================================================
__global__ __launch_bounds__(256) void k_conv(const float* __restrict__ src,
                                              __nv_bfloat16* __restrict__ hi, int n4) {
    int stride = gridDim.x * blockDim.x;
    for (int g = blockIdx.x * blockDim.x + threadIdx.x; g < n4; g += stride) {
        float4 v = *(const float4*)(src + (size_t)g * 4);
        uint2 h;
        h.x = ((uint32_t)__bfloat16_as_ushort(__float2bfloat16_rn(v.y)) << 16)
            | __bfloat16_as_ushort(__float2bfloat16_rn(v.x));
        h.y = ((uint32_t)__bfloat16_as_ushort(__float2bfloat16_rn(v.w)) << 16)
            | __bfloat16_as_ushort(__float2bfloat16_rn(v.z));
        ((uint2*)hi)[g] = h;
    }
}

// ============================================================
// K2: ||e_k||^2 (fp32, one warp per code row)
// ============================================================
__global__ __launch_bounds__(256) void k_enorm2(const float* __restrict__ E) {
    int warp = (blockIdx.x * blockDim.x + threadIdx.x) >> 5;
    int lane = threadIdx.x & 31;
    if (warp >= KC) return;
    const float* row = E + (size_t)warp * DIM;
    float s = 0.0f;
    #pragma unroll
    for (int d = lane * 4; d < DIM; d += 32 * 4) {
        float4 v = *(const float4*)(row + d);
        s = fmaf(v.x, v.x, s); s = fmaf(v.y, v.y, s);
        s = fmaf(v.z, v.z, s); s = fmaf(v.w, v.w, s);
    }
    #pragma unroll
    for (int o = 16; o; o >>= 1) s += __shfl_xor_sync(0xffffffffu, s, o);
    if (lane == 0) g_enorm2[warp] = s;
}

// ============================================================
// K3: bf16 hh-only mma.sync GEMM + per-thread top-2 candidates
// CTA: 128 rows x 64 n-tiles(128 codes); BK=32.
// 8 warps as 4 (rows) x 2 (cols); warp tile 32x64.
// smem: double-buffered {Ah, Bh}, 128x32 bf16 each, 80B row stride.
// 2 CTAs/SM (40KB smem, <=128 regs) -> grid 256 fits in ONE wave.
// ============================================================
#define TILE_B   10240
#define BUF_B    20480
#define SMEM_MMA (2 * BUF_B)

__device__ __forceinline__ void stage_chunk(uint32_t sbuf, int mt, int t, int kc, int tid) {
    // 1024 x 16B segments: tiles {Ah, Bh}, each 128 rows x 64B
    const char* gb[2] = { (const char*)g_xhi, (const char*)g_ehi };
    const int rb[2] = { mt * 128, t * 128 };
    #pragma unroll
    for (int i = 0; i < 4; ++i) {
        const int tile = i >> 1;
        int r = ((i & 1) << 6) + (tid >> 2);
        int c = tid & 3;
        const char* src = gb[tile] + (size_t)(rb[tile] + r) * (DIM * 2) + kc * 64 + c * 16;
        cp16(sbuf + tile * TILE_B + r * 80 + c * 16, src);
    }
}

__global__ __launch_bounds__(256, 2) void k_argmin_mma() {
    extern __shared__ char smem[];
    const uint32_t sb = smem_u32(smem);
    const int tid = threadIdx.x;
    const int lane = tid & 31;
    const int wid = tid >> 5;
    const int wr = wid >> 1;           // 0..3 : 32-row band
    const int wc = wid & 1;            // 0..1 : 64-col band
    const int mt = blockIdx.x;

    const uint32_t offA = (uint32_t)((wr * 32 + (lane & 15)) * 80 + ((lane >> 4) & 1) * 16);
    const uint32_t offB = (uint32_t)((wc * 64 + (lane & 7) + ((lane >> 4) & 1) * 8) * 80
                                     + ((lane >> 3) & 1) * 16);

    // per-thread top-2 over 4 row slots
    float v1[4], v2[4];
    int   i1[4], i2[4];
    #pragma unroll
    for (int i = 0; i < 4; ++i) { v1[i] = FLT_MAX; v2[i] = FLT_MAX; i1[i] = 0; i2[i] = 0; }

    #pragma unroll 1
    for (int t = 0; t < KC / 128; ++t) {
        float acc[2][8][4];
        #pragma unroll
        for (int m = 0; m < 2; ++m)
            #pragma unroll
            for (int n = 0; n < 8; ++n)
                #pragma unroll
                for (int r = 0; r < 4; ++r) acc[m][n][r] = 0.0f;

        stage_chunk(sb, mt, t, 0, tid);
        cp_commit();

        #pragma unroll 1
        for (int kc = 0; kc < DIM / 32; ++kc) {
            cp_wait0();
            __syncthreads();
            if (kc + 1 < DIM / 32) {
                stage_chunk(sb + ((kc + 1) & 1) * BUF_B, mt, t, kc + 1, tid);
                cp_commit();
            }
            const uint32_t buf = sb + (kc & 1) * BUF_B;

            #pragma unroll
            for (int ks = 0; ks < 2; ++ks) {
                uint32_t aH[2][4], bH[4][4];
                #pragma unroll
                for (int m = 0; m < 2; ++m)
                    ldsm4(aH[m], buf + offA + m * (16 * 80) + ks * 32);
                #pragma unroll
                for (int p = 0; p < 4; ++p)
                    ldsm4(bH[p], buf + TILE_B + offB + p * (16 * 80) + ks * 32);
                #pragma unroll
                for (int m = 0; m < 2; ++m)
                    #pragma unroll
                    for (int n = 0; n < 8; ++n)
                        mma16816(acc[m][n], aH[m], &bH[n >> 1][(n & 1) * 2]);
            }
            __syncthreads();
        }

        // fold into per-slot top-2
        #pragma unroll
        for (int n = 0; n < 8; ++n) {
            const int colb = t * 128 + wc * 64 + n * 8 + 2 * (lane & 3);
            const float en0 = __ldg(&g_enorm2[colb]);
            const float en1 = __ldg(&g_enorm2[colb + 1]);
            #pragma unroll
            for (int m = 0; m < 2; ++m) {
                #pragma unroll
                for (int r = 0; r < 4; ++r) {
                    const float en = (r & 1) ? en1 : en0;
                    const int col = colb + (r & 1);
                    const int rs = m * 2 + (r >> 1);
                    float s = fmaf(-2.0f, acc[m][n][r], en);
                    if (s < v1[rs]) {
                        v2[rs] = v1[rs]; i2[rs] = i1[rs];
                        v1[rs] = s;      i1[rs] = col;
                    } else if (s < v2[rs]) {
                        v2[rs] = s;      i2[rs] = col;
                    }
                }
            }
        }
    }

    // dump candidates: per row 16 = 8 owner threads x top-2
    __syncthreads();
    int* ci = (int*)smem;       // 128 x 16 ints = 8 KB
    #pragma unroll
    for (int m = 0; m < 2; ++m)
        #pragma unroll
        for (int h = 0; h < 2; ++h) {
            int row = wr * 32 + m * 16 + h * 8 + (lane >> 2);
            int slot = wc * 8 + (lane & 3) * 2;
            ci[row * 16 + slot]     = i1[m * 2 + h];
            ci[row * 16 + slot + 1] = i2[m * 2 + h];
        }
    __syncthreads();
    #pragma unroll
    for (int j = 0; j < 8; ++j) {
        int lin = tid * 8 + j;      // 0..2047
        g_cand[(size_t)mt * 128 * NCAND + lin] = ci[lin];
    }
}

// ============================================================
// K3b: exact fp32 re-rank of 16 candidates per row
// block = 1 row, 128 threads (4 warps x 4 candidates each).
// ============================================================
__global__ __launch_bounds__(128) void k_rerank(const float* __restrict__ X,
                                                const float* __restrict__ E) {
    __shared__ float xs[DIM];
    __shared__ float wv[4];
    __shared__ int   wi[4];
    const int row = blockIdx.x;
    const int tid = threadIdx.x;
    const int lane = tid & 31;
    const int warp = tid >> 5;

    *(float4*)(xs + tid * 4) = *(const float4*)(X + (size_t)row * DIM + tid * 4);
    __syncthreads();

    float bestv = FLT_MAX; int besti = 0x7fffffff;
    #pragma unroll
    for (int c = 0; c < 4; ++c) {
        const int idx = g_cand[(size_t)row * NCAND + warp * 4 + c];
        const float* er = E + (size_t)idx * DIM;
        float dot = 0.0f;
        #pragma unroll
        for (int j = 0; j < 4; ++j) {
            float4 e = *(const float4*)(er + j * 128 + lane * 4);
            float4 x = *(const float4*)(xs + j * 128 + lane * 4);
            dot = fmaf(x.x, e.x, dot); dot = fmaf(x.y, e.y, dot);
            dot = fmaf(x.z, e.z, dot); dot = fmaf(x.w, e.w, dot);
        }
        #pragma unroll
        for (int o = 16; o; o >>= 1) dot += __shfl_xor_sync(0xffffffffu, dot, o);
        float s = fmaf(-2.0f, dot, __ldg(&g_enorm2[idx]));
        if (s < bestv || (s == bestv && idx < besti)) { bestv = s; besti = idx; }
    }
    if (lane == 0) { wv[warp] = bestv; wi[warp] = besti; }
    __syncthreads();
    if (tid == 0) {
        float bv = wv[0]; int bi = wi[0];
        #pragma unroll
        for (int w = 1; w < 4; ++w) {
            if (wv[w] < bv || (wv[w] == bv && wi[w] < bi)) { bv = wv[w]; bi = wi[w]; }
        }
        g_idx[row] = bi;
    }
}

// ============================================================
// K4: gather quantized, loss partial, counts, dw scatter-add
// ============================================================
__global__ __launch_bounds__(128) void k_gather(const float* __restrict__ X,
                                                const float* __restrict__ E,
                                                float* __restrict__ out) {
    __shared__ float warp_sums[4];
    int row = blockIdx.x;
    int idx = g_idx[row];
    if (threadIdx.x == 0) atomicAdd(&g_counts[idx], 1.0f);

    const float* xr = X + (size_t)row * DIM;
    const float* er = E + (size_t)idx * DIM;
    float* dwr = g_dw + (size_t)idx * DIM;
    float* qr  = out + O_Q + (size_t)row * DIM;

    int d = threadIdx.x * 4;
    float4 q = *(const float4*)(er + d);
    float4 x = *(const float4*)(xr + d);
    *(float4*)(qr + d) = q;
    atomicAdd(dwr + d + 0, x.x);
    atomicAdd(dwr + d + 1, x.y);
    atomicAdd(dwr + d + 2, x.z);
    atomicAdd(dwr + d + 3, x.w);

    float dx = q.x - x.x, dy = q.y - x.y, dz = q.z - x.z, dw = q.w - x.w;
    float ls = dx * dx + dy * dy + dz * dz + dw * dw;
    #pragma unroll
    for (int o = 16; o; o >>= 1) ls += __shfl_xor_sync(0xffffffffu, ls, o);
    int lane = threadIdx.x & 31, warp = threadIdx.x >> 5;
    if (lane == 0) warp_sums[warp] = ls;
    __syncthreads();
    if (threadIdx.x == 0) {
        float s = warp_sums[0] + warp_sums[1] + warp_sums[2] + warp_sums[3];
        atomicAdd(&g_loss_sum, s);
    }
}

// ============================================================
// K5a: EMA cluster-size pre + global sums
// ============================================================
__global__ __launch_bounds__(256) void k_stats1(const float* __restrict__ cs_in) {
    __shared__ float sn[8], sp[8];
    int k = blockIdx.x * 256 + threadIdx.x;
    float cnt = g_counts[k];
    float pre = fmaf(cs_in[k], DECAYF, OMDF * cnt);
    g_cs_pre[k] = pre;
    float p = cnt * (1.0f / (float)NROWS);
    float pl = p * logf(p + 1e-10f);
    float ns = pre, ps = pl;
    #pragma unroll
    for (int o = 16; o; o >>= 1) {
        ns += __shfl_xor_sync(0xffffffffu, ns, o);
        ps += __shfl_xor_sync(0xffffffffu, ps, o);
    }
    int lane = threadIdx.x & 31, warp = threadIdx.x >> 5;
    if (lane == 0) { sn[warp] = ns; sp[warp] = ps; }
    __syncthreads();
    if (threadIdx.x == 0) {
        float a = 0.0f, b = 0.0f;
        #pragma unroll
        for (int w = 0; w < 8; ++w) { a += sn[w]; b += sp[w]; }
        atomicAdd(&g_n_sum, a);
        atomicAdd(&g_plogp_sum, b);
    }
}

// ============================================================
// K5b: finalize new_cs + scalars
// ============================================================
__global__ __launch_bounds__(256) void k_stats2(float* __restrict__ out) {
    int k = blockIdx.x * 256 + threadIdx.x;
    float n = g_n_sum;
    float ncs = (g_cs_pre[k] + EPSF) / (n + (float)KC * EPSF) * n;
    out[O_CS + k] = ncs;
    if (blockIdx.x == 0 && threadIdx.x == 0) {
        out[O_LOSS] = 0.25f * (g_loss_sum / (float)(NROWS * DIM));
        out[O_PERP] = expf(-g_plogp_sum);
    }
}

// ============================================================
// K6: new_w + new_embedding (float2 stores: regions only 8B aligned)
// ============================================================
__global__ __launch_bounds__(256) void k_final(const float* __restrict__ ema_w,
                                               float* __restrict__ out) {
    const float* ncs = out + O_CS;
    int i = blockIdx.x * blockDim.x + threadIdx.x;
    int total = KC * DIM / 4;
    int stride = gridDim.x * blockDim.x;
    for (; i < total; i += stride) {
        int e = i * 4;
        int k = e >> 9;
        float4 w  = *(const float4*)(ema_w + e);
        float4 dv = *(const float4*)(g_dw + e);
        float4 nw;
        nw.x = fmaf(w.x, DECAYF, OMDF * dv.x);
        nw.y = fmaf(w.y, DECAYF, OMDF * dv.y);
        nw.z = fmaf(w.z, DECAYF, OMDF * dv.z);
        nw.w = fmaf(w.w, DECAYF, OMDF * dv.w);
        *(float2*)(out + O_W + e)     = make_float2(nw.x, nw.y);
        *(float2*)(out + O_W + e + 2) = make_float2(nw.z, nw.w);
        float inv = 1.0f / ncs[k];
        *(float2*)(out + O_EMB + e)     = make_float2(nw.x * inv, nw.y * inv);
        *(float2*)(out + O_EMB + e + 2) = make_float2(nw.z * inv, nw.w * inv);
    }
}

// ============================================================
extern "C" void kernel_launch(void* const* d_in, const int* in_sizes, int n_in,
                              void* d_out, int out_size) {
    const float* X     = (const float*)d_in[0];
    const float* E     = (const float*)d_in[1];
    const float* cs    = (const float*)d_in[2];
    const float* ema_w = (const float*)d_in[3];
    float* out = (float*)d_out;

    cudaFuncSetAttribute(k_argmin_mma, cudaFuncAttributeMaxDynamicSharedMemorySize, SMEM_MMA);

    __nv_bfloat16 *xhi, *ehi;
    cudaGetSymbolAddress((void**)&xhi, g_xhi);
    cudaGetSymbolAddress((void**)&ehi, g_ehi);

    k_init  <<<4096, 256>>>();
    k_conv  <<<2048, 256>>>(X, xhi, NROWS * DIM / 4);
    k_conv  <<<1024, 256>>>(E, ehi, KC * DIM / 4);
    k_enorm2<<<KC / 8, 256>>>(E);
    k_argmin_mma<<<NROWS / 128, 256, SMEM_MMA>>>();
    k_rerank<<<NROWS, 128>>>(X, E);
    k_gather<<<NROWS, 128>>>(X, E, out);
    k_stats1<<<KC / 256, 256>>>(cs);
    k_stats2<<<KC / 256, 256>>>(out);
    k_final <<<2048, 256>>>(ema_w, out);
}

// round 6
// speedup vs baseline: 5.9778x; 1.1561x over previous
#include <cuda_runtime.h>
#include <cuda_fp16.h>
#include <math.h>
#include <float.h>
#include <stdint.h>

// Problem constants
#define NROWS 32768
#define KC    8192
#define DIM   512

#define DECAYF 0.99f
#define OMDF   0.01f
#define EPSF   1e-5f

#define NCAND 32          // candidates per row (16 owner threads x top-2)
#define RERANK_THRESH 2.0f

// ============================================================
// scratch (device globals)
// ============================================================
__device__ float g_enorm2[KC];
__device__ int   g_idx[NROWS];
__device__ unsigned int g_cand[NROWS * NCAND];
__device__ float g_counts[KC];
__device__ float g_dw[KC * DIM];
__device__ float g_cs_pre[KC];
__device__ float g_loss_sum;
__device__ float g_n_sum;
__device__ float g_plogp_sum;

// fp16 operands, row-major [rows][512]
__device__ __half g_xh[NROWS * DIM];
__device__ __half g_eh[KC * DIM];

// ---- output layout (O_EMB/O_W only 8-byte aligned -> float2 there) ----
#define O_Q    0
#define O_LOSS (NROWS * DIM)
#define O_PERP (O_LOSS + 1)
#define O_EMB  (O_PERP + 1)
#define O_CS   (O_EMB + KC * DIM)
#define O_W    (O_CS + KC)

// ============================================================
// PTX helpers (baseline compute_100 = sm_80+ features only)
// ============================================================
__device__ __forceinline__ uint32_t smem_u32(const void* p) {
    uint32_t a;
    asm("{ .reg .u64 t; cvta.to.shared.u64 t, %1; cvt.u32.u64 %0, t; }" : "=r"(a) : "l"(p));
    return a;
}
__device__ __forceinline__ void cp16(uint32_t dst, const void* src) {
    asm volatile("cp.async.cg.shared.global [%0], [%1], 16;" :: "r"(dst), "l"(src) : "memory");
}
__device__ __forceinline__ void cp_commit() { asm volatile("cp.async.commit_group;" ::: "memory"); }
__device__ __forceinline__ void cp_wait0()  { asm volatile("cp.async.wait_group 0;" ::: "memory"); }

__device__ __forceinline__ void ldsm4(uint32_t* r, uint32_t addr) {
    asm volatile("ldmatrix.sync.aligned.m8n8.x4.shared.b16 {%0,%1,%2,%3}, [%4];"
        : "=r"(r[0]), "=r"(r[1]), "=r"(r[2]), "=r"(r[3]) : "r"(addr));
}
// f16 x f16 -> f16 accumulate
__device__ __forceinline__ void mma16816h(uint32_t* c, const uint32_t* a, const uint32_t* b) {
    asm volatile(
        "mma.sync.aligned.m16n8k16.row.col.f16.f16.f16.f16 "
        "{%0,%1}, {%2,%3,%4,%5}, {%6,%7}, {%0,%1};"
        : "+r"(c[0]), "+r"(c[1])
        : "r"(a[0]), "r"(a[1]), "r"(a[2]), "r"(a[3]), "r"(b[0]), "r"(b[1]));
}

// ============================================================
// K0: zero scratch accumulators
// ============================================================
__global__ __launch_bounds__(256) void k_init() {
    int gid = blockIdx.x * blockDim.x + threadIdx.x;
    int stride = gridDim.x * blockDim.x;
    for (int i = gid; i < KC * DIM; i += stride) g_dw[i] = 0.0f;
    if (gid < KC) g_counts[gid] = 0.0f;
    if (gid == 0) { g_loss_sum = 0.0f; g_n_sum = 0.0f; g_plogp_sum = 0.0f; }
}

// ============================================================
// K1: fp32 -> fp16, row-major
// ============================================================
__global__ __launch_bounds__(256) void k_conv(const float* __restrict__ src,
                                              __half* __restrict__ dst, int n4) {
    int stride = gridDim.x * blockDim.x;
    for (int g = blockIdx.x * blockDim.x + threadIdx.x; g < n4; g += stride) {
        float4 v = *(const float4*)(src + (size_t)g * 4);
        __half2 a = __floats2half2_rn(v.x, v.y);
        __half2 b = __floats2half2_rn(v.z, v.w);
        uint2 h;
        h.x = *(uint32_t*)&a;
        h.y = *(uint32_t*)&b;
        ((uint2*)dst)[g] = h;
    }
}

// ============================================================
// K2: ||e_k||^2 (fp32, one warp per code row)
// ============================================================
__global__ __launch_bounds__(256) void k_enorm2(const float* __restrict__ E) {
    int warp = (blockIdx.x * blockDim.x + threadIdx.x) >> 5;
    int lane = threadIdx.x & 31;
    if (warp >= KC) return;
    const float* row = E + (size_t)warp * DIM;
    float s = 0.0f;
    #pragma unroll
    for (int d = lane * 4; d < DIM; d += 32 * 4) {
        float4 v = *(const float4*)(row + d);
        s = fmaf(v.x, v.x, s); s = fmaf(v.y, v.y, s);
        s = fmaf(v.z, v.z, s); s = fmaf(v.w, v.w, s);
    }
    #pragma unroll
    for (int o = 16; o; o >>= 1) s += __shfl_xor_sync(0xffffffffu, s, o);
    if (lane == 0) g_enorm2[warp] = s;
}

// ============================================================
// K3: fp16 mma.sync GEMM + per-thread top-2 candidates
// CTA tile: 128 rows x 256 cols per n-tile; 32 n-tiles; BK=32.
// 8 warps as 2 (row) x 4 (col); warp tile 64x64; f16 accumulators.
// smem: double-buffered {A 128x32, B 256x32} halves, 80B row stride.
// top-2 per (thread, rowslot) lives in smem [slot][tid].
// 2 CTAs/SM -> grid 256 in <=1 wave equivalent.
// ============================================================
#define TILE_A   10240                 // 128 * 80
#define TILE_BB  20480                 // 256 * 80
#define BUF_B    (TILE_A + TILE_BB)    // 30720
#define TOP2V    (2 * BUF_B)           // float2 [8][256] = 16384
#define TOP2I    (TOP2V + 16384)       // uint32 [8][256] = 8192
#define SMEM_MMA (TOP2I + 8192)        // 86016

__device__ __forceinline__ void stage_chunk(uint32_t sbuf, int mt, int t, int kc, int tid) {
    #pragma unroll
    for (int i = 0; i < 2; ++i) {       // A: 512 x 16B segments
        int seg = tid + i * 256;
        int r = seg >> 2, c = seg & 3;
        const char* src = (const char*)g_xh + ((size_t)(mt * 128 + r) * DIM + kc * 32) * 2 + c * 16;
        cp16(sbuf + r * 80 + c * 16, src);
    }
    #pragma unroll
    for (int i = 0; i < 4; ++i) {       // B: 1024 x 16B segments
        int seg = tid + i * 256;
        int r = seg >> 2, c = seg & 3;
        const char* src = (const char*)g_eh + ((size_t)(t * 256 + r) * DIM + kc * 32) * 2 + c * 16;
        cp16(sbuf + TILE_A + r * 80 + c * 16, src);
    }
}

__global__ __launch_bounds__(256, 2) void k_argmin_mma() {
    extern __shared__ char smem[];
    const uint32_t sb = smem_u32(smem);
    const int tid = threadIdx.x;
    const int lane = tid & 31;
    const int wid = tid >> 5;
    const int wr = wid >> 2;           // 0..1 : 64-row band
    const int wc = wid & 3;            // 0..3 : 64-col band
    const int mt = blockIdx.x;

    const uint32_t offA = (uint32_t)((wr * 64 + (lane & 15)) * 80 + ((lane >> 4) & 1) * 16);
    const uint32_t offB = (uint32_t)(TILE_A + ((lane & 7) + ((lane >> 4) & 1) * 8) * 80
                                     + ((lane >> 3) & 1) * 16);
    const int wcol = wc * 64;          // warp col base within tile (B rows loaded at +wcol)

    // init per-thread top-2 (8 row slots) in smem, layout [slot][tid]
    #pragma unroll
    for (int s = 0; s < 8; ++s) {
        *(float2*)(smem + TOP2V + (s * 256 + tid) * 8) = make_float2(FLT_MAX, FLT_MAX);
        *(uint32_t*)(smem + TOP2I + (s * 256 + tid) * 4) = 0;
    }

    #pragma unroll 1
    for (int t = 0; t < KC / 256; ++t) {
        uint32_t acc[4][8][2];
        #pragma unroll
        for (int m = 0; m < 4; ++m)
            #pragma unroll
            for (int n = 0; n < 8; ++n) { acc[m][n][0] = 0u; acc[m][n][1] = 0u; }

        stage_chunk(sb, mt, t, 0, tid);
        cp_commit();

        #pragma unroll 1
        for (int kc = 0; kc < DIM / 32; ++kc) {
            cp_wait0();
            __syncthreads();
            if (kc + 1 < DIM / 32) {
                stage_chunk(sb + ((kc + 1) & 1) * BUF_B, mt, t, kc + 1, tid);
                cp_commit();
            }
            const uint32_t buf = sb + (kc & 1) * BUF_B;

            #pragma unroll
            for (int ks = 0; ks < 2; ++ks) {
                uint32_t aH[4][4], bH[4][4];
                #pragma unroll
                for (int m = 0; m < 4; ++m)
                    ldsm4(aH[m], buf + offA + m * (16 * 80) + ks * 32);
                #pragma unroll
                for (int p = 0; p < 4; ++p)
                    ldsm4(bH[p], buf + offB + (wcol + p * 16) * 80 + ks * 32);
                #pragma unroll
                for (int m = 0; m < 4; ++m)
                    #pragma unroll
                    for (int p = 0; p < 4; ++p) {
                        mma16816h(acc[m][p * 2],     aH[m], &bH[p][0]);
                        mma16816h(acc[m][p * 2 + 1], aH[m], &bH[p][2]);
                    }
            }
            __syncthreads();
        }

        // fold tile into per-slot top-2 (own-thread smem slots, no sync needed)
        float enc[8][2];
        #pragma unroll
        for (int n = 0; n < 8; ++n) {
            int c0 = t * 256 + wcol + n * 8 + (lane & 3) * 2;
            enc[n][0] = __ldg(&g_enorm2[c0]);
            enc[n][1] = __ldg(&g_enorm2[c0 + 1]);
        }
        #pragma unroll
        for (int m = 0; m < 4; ++m)
            #pragma unroll
            for (int h = 0; h < 2; ++h) {
                const int slot = m * 2 + h;
                float2 v = *(float2*)(smem + TOP2V + (slot * 256 + tid) * 8);
                uint32_t ip = *(uint32_t*)(smem + TOP2I + (slot * 256 + tid) * 4);
                int i1 = ip >> 16, i2 = ip & 0xffff;
                #pragma unroll
                for (int n = 0; n < 8; ++n) {
                    const int c0 = t * 256 + wcol + n * 8 + (lane & 3) * 2;
                    __half2 hv = *(__half2*)&acc[m][n][h];
                    float s0 = fmaf(-2.0f, __low2float(hv),  enc[n][0]);
                    float s1 = fmaf(-2.0f, __high2float(hv), enc[n][1]);
                    if (s0 < v.x)      { v.y = v.x; i2 = i1; v.x = s0; i1 = c0; }
                    else if (s0 < v.y) { v.y = s0; i2 = c0; }
                    if (s1 < v.x)      { v.y = v.x; i2 = i1; v.x = s1; i1 = c0 + 1; }
                    else if (s1 < v.y) { v.y = s1; i2 = c0 + 1; }
                }
                *(float2*)(smem + TOP2V + (slot * 256 + tid) * 8) = v;
                *(uint32_t*)(smem + TOP2I + (slot * 256 + tid) * 4) = (uint32_t)(i1 << 16) | (uint32_t)i2;
            }
    }

    // dump candidates: key = (f16(approx) << 16) | col ; [row][32] in smem
    __syncthreads();
    uint32_t* keys = (uint32_t*)smem;          // 128*32*4 = 16KB (buffer area reuse)
    #pragma unroll
    for (int m = 0; m < 4; ++m)
        #pragma unroll
        for (int h = 0; h < 2; ++h) {
            const int slot = m * 2 + h;
            float2 v = *(float2*)(smem + TOP2V + (slot * 256 + tid) * 8);
            uint32_t ip = *(uint32_t*)(smem + TOP2I + (slot * 256 + tid) * 4);
            int row = wr * 64 + m * 16 + h * 8 + (lane >> 2);
            int ent = wc * 8 + (lane & 3) * 2;
            uint32_t k1 = ((uint32_t)__half_as_ushort(__float2half_rn(v.x)) << 16) | (ip >> 16);
            uint32_t k2 = ((uint32_t)__half_as_ushort(__float2half_rn(v.y)) << 16) | (ip & 0xffff);
            keys[row * 32 + ent]     = k1;
            keys[row * 32 + ent + 1] = k2;
        }
    __syncthreads();
    #pragma unroll
    for (int j = 0; j < 16; ++j) {
        int lin = tid + j * 256;               // 0..4095
        g_cand[(size_t)mt * (128 * NCAND) + lin] = keys[lin];
    }
}

// ============================================================
// K3b: threshold-gated exact fp32 re-rank
// block = 1 row, 128 threads; usually computes ~1 exact dot.
// ============================================================
__global__ __launch_bounds__(128) void k_rerank(const float* __restrict__ X,
                                                const float* __restrict__ E) {
    __shared__ float xs[DIM];
    __shared__ unsigned int keys[NCAND];
    __shared__ unsigned int mkey;
    __shared__ unsigned long long res;
    const int row = blockIdx.x;
    const int tid = threadIdx.x;
    const int lane = tid & 31;
    const int warp = tid >> 5;

    if (tid < NCAND) keys[tid] = g_cand[(size_t)row * NCAND + tid];
    *(float4*)(xs + tid * 4) = *(const float4*)(X + (size_t)row * DIM + tid * 4);
    if (tid == 0) res = ~0ull;
    __syncthreads();

    if (tid < 32) {
        unsigned int m = __reduce_min_sync(0xffffffffu, keys[tid]);
        if (tid == 0) mkey = m;
    }
    __syncthreads();

    const float thresh = __half2float(__ushort_as_half((unsigned short)(mkey >> 16)))
                         + RERANK_THRESH;

    for (int c = warp; c < NCAND; c += 4) {
        unsigned int k = keys[c];
        float v = __half2float(__ushort_as_half((unsigned short)(k >> 16)));
        if (v <= thresh) {
            int col = (int)(k & 0xffffu);
            const float* er = E + (size_t)col * DIM;
            float dot = 0.0f;
            #pragma unroll
            for (int j = 0; j < 4; ++j) {
                float4 e = *(const float4*)(er + j * 128 + lane * 4);
                float4 x = *(const float4*)(xs + j * 128 + lane * 4);
                dot = fmaf(x.x, e.x, dot); dot = fmaf(x.y, e.y, dot);
                dot = fmaf(x.z, e.z, dot); dot = fmaf(x.w, e.w, dot);
            }
            #pragma unroll
            for (int o = 16; o; o >>= 1) dot += __shfl_xor_sync(0xffffffffu, dot, o);
            if (lane == 0) {
                float s = fmaf(-2.0f, dot, __ldg(&g_enorm2[col]));
                unsigned long long key64 =
                    ((unsigned long long)__float_as_uint(s) << 32) | (unsigned int)col;
                atomicMin(&res, key64);
            }
        }
    }
    __syncthreads();
    if (tid == 0) g_idx[row] = (int)(res & 0xffffffffull);
}

// ============================================================
// K4: gather quantized, loss partial, counts, dw scatter-add
// ============================================================
__global__ __launch_bounds__(128) void k_gather(const float* __restrict__ X,
                                                const float* __restrict__ E,
                                                float* __restrict__ out) {
    __shared__ float warp_sums[4];
    int row = blockIdx.x;
    int idx = g_idx[row];
    if (threadIdx.x == 0) atomicAdd(&g_counts[idx], 1.0f);

    const float* xr = X + (size_t)row * DIM;
    const float* er = E + (size_t)idx * DIM;
    float* dwr = g_dw + (size_t)idx * DIM;
    float* qr  = out + O_Q + (size_t)row * DIM;

    int d = threadIdx.x * 4;
    float4 q = *(const float4*)(er + d);
    float4 x = *(const float4*)(xr + d);
    *(float4*)(qr + d) = q;
    atomicAdd(dwr + d + 0, x.x);
    atomicAdd(dwr + d + 1, x.y);
    atomicAdd(dwr + d + 2, x.z);
    atomicAdd(dwr + d + 3, x.w);

    float dx = q.x - x.x, dy = q.y - x.y, dz = q.z - x.z, dw = q.w - x.w;
    float ls = dx * dx + dy * dy + dz * dz + dw * dw;
    #pragma unroll
    for (int o = 16; o; o >>= 1) ls += __shfl_xor_sync(0xffffffffu, ls, o);
    int lane = threadIdx.x & 31, warp = threadIdx.x >> 5;
    if (lane == 0) warp_sums[warp] = ls;
    __syncthreads();
    if (threadIdx.x == 0) {
        float s = warp_sums[0] + warp_sums[1] + warp_sums[2] + warp_sums[3];
        atomicAdd(&g_loss_sum, s);
    }
}

// ============================================================
// K5a: EMA cluster-size pre + global sums
// ============================================================
__global__ __launch_bounds__(256) void k_stats1(const float* __restrict__ cs_in) {
    __shared__ float sn[8], sp[8];
    int k = blockIdx.x * 256 + threadIdx.x;
    float cnt = g_counts[k];
    float pre = fmaf(cs_in[k], DECAYF, OMDF * cnt);
    g_cs_pre[k] = pre;
    float p = cnt * (1.0f / (float)NROWS);
    float pl = p * logf(p + 1e-10f);
    float ns = pre, ps = pl;
    #pragma unroll
    for (int o = 16; o; o >>= 1) {
        ns += __shfl_xor_sync(0xffffffffu, ns, o);
        ps += __shfl_xor_sync(0xffffffffu, ps, o);
    }
    int lane = threadIdx.x & 31, warp = threadIdx.x >> 5;
    if (lane == 0) { sn[warp] = ns; sp[warp] = ps; }
    __syncthreads();
    if (threadIdx.x == 0) {
        float a = 0.0f, b = 0.0f;
        #pragma unroll
        for (int w = 0; w < 8; ++w) { a += sn[w]; b += sp[w]; }
        atomicAdd(&g_n_sum, a);
        atomicAdd(&g_plogp_sum, b);
    }
}

// ============================================================
// K5b: finalize new_cs + scalars
// ============================================================
__global__ __launch_bounds__(256) void k_stats2(float* __restrict__ out) {
    int k = blockIdx.x * 256 + threadIdx.x;
    float n = g_n_sum;
    float ncs = (g_cs_pre[k] + EPSF) / (n + (float)KC * EPSF) * n;
    out[O_CS + k] = ncs;
    if (blockIdx.x == 0 && threadIdx.x == 0) {
        out[O_LOSS] = 0.25f * (g_loss_sum / (float)(NROWS * DIM));
        out[O_PERP] = expf(-g_plogp_sum);
    }
}

// ============================================================
// K6: new_w + new_embedding (float2 stores: regions only 8B aligned)
// ============================================================
__global__ __launch_bounds__(256) void k_final(const float* __restrict__ ema_w,
                                               float* __restrict__ out) {
    const float* ncs = out + O_CS;
    int i = blockIdx.x * blockDim.x + threadIdx.x;
    int total = KC * DIM / 4;
    int stride = gridDim.x * blockDim.x;
    for (; i < total; i += stride) {
        int e = i * 4;
        int k = e >> 9;
        float4 w  = *(const float4*)(ema_w + e);
        float4 dv = *(const float4*)(g_dw + e);
        float4 nw;
        nw.x = fmaf(w.x, DECAYF, OMDF * dv.x);
        nw.y = fmaf(w.y, DECAYF, OMDF * dv.y);
        nw.z = fmaf(w.z, DECAYF, OMDF * dv.z);
        nw.w = fmaf(w.w, DECAYF, OMDF * dv.w);
        *(float2*)(out + O_W + e)     = make_float2(nw.x, nw.y);
        *(float2*)(out + O_W + e + 2) = make_float2(nw.z, nw.w);
        float inv = 1.0f / ncs[k];
        *(float2*)(out + O_EMB + e)     = make_float2(nw.x * inv, nw.y * inv);
        *(float2*)(out + O_EMB + e + 2) = make_float2(nw.z * inv, nw.w * inv);
    }
}

// ============================================================
extern "C" void kernel_launch(void* const* d_in, const int* in_sizes, int n_in,
                              void* d_out, int out_size) {
    const float* X     = (const float*)d_in[0];
    const float* E     = (const float*)d_in[1];
    const float* cs    = (const float*)d_in[2];
    const float* ema_w = (const float*)d_in[3];
    float* out = (float*)d_out;

    cudaFuncSetAttribute(k_argmin_mma, cudaFuncAttributeMaxDynamicSharedMemorySize, SMEM_MMA);

    __half *xh, *eh;
    cudaGetSymbolAddress((void**)&xh, g_xh);
    cudaGetSymbolAddress((void**)&eh, g_eh);

    k_init  <<<4096, 256>>>();
    k_conv  <<<2048, 256>>>(X, xh, NROWS * DIM / 4);
    k_conv  <<<1024, 256>>>(E, eh, KC * DIM / 4);
    k_enorm2<<<KC / 8, 256>>>(E);
    k_argmin_mma<<<NROWS / 128, 256, SMEM_MMA>>>();
    k_rerank<<<NROWS, 128>>>(X, E);
    k_gather<<<NROWS, 128>>>(X, E, out);
    k_stats1<<<KC / 256, 256>>>(cs);
    k_stats2<<<KC / 256, 256>>>(out);
    k_final <<<2048, 256>>>(ema_w, out);
}

// round 7
// speedup vs baseline: 9.1231x; 1.5262x over previous
#include <cuda_runtime.h>
#include <cuda_fp16.h>
#include <math.h>
#include <float.h>
#include <stdint.h>

// Problem constants
#define NROWS 32768
#define KC    8192
#define DIM   512

#define DECAYF 0.99f
#define OMDF   0.01f
#define EPSF   1e-5f

#define NCAND 24              // 8 owner threads x top-3 per row
#define RERANK_THRESH 10.0f   // int8 distance err sigma ~1.2 -> 8.6 sigma gate
#define QSCALE 16.0f          // int8 quant scale; dot = acc/256; s = en - acc/128

// ============================================================
// scratch (device globals)
// ============================================================
__device__ float g_enorm2[KC];
__device__ unsigned int g_cand[NROWS * NCAND];
__device__ float g_counts[KC];
__device__ float g_dw[KC * DIM];
__device__ float g_cs_pre[KC];
__device__ float g_loss_sum;
__device__ float g_n_sum;
__device__ float g_plogp_sum;

// int8 operands, row-major [rows][512]
__device__ int8_t g_xs8[NROWS * DIM];
__device__ int8_t g_es8[KC * DIM];

// ---- output layout (O_EMB/O_W only 8-byte aligned -> float2 there) ----
#define O_Q    0
#define O_LOSS (NROWS * DIM)
#define O_PERP (O_LOSS + 1)
#define O_EMB  (O_PERP + 1)
#define O_CS   (O_EMB + KC * DIM)
#define O_W    (O_CS + KC)

// ============================================================
// PTX helpers (baseline compute_100 = sm_80+ features only)
// ============================================================
__device__ __forceinline__ uint32_t smem_u32(const void* p) {
    uint32_t a;
    asm("{ .reg .u64 t; cvta.to.shared.u64 t, %1; cvt.u32.u64 %0, t; }" : "=r"(a) : "l"(p));
    return a;
}
__device__ __forceinline__ void cp16(uint32_t dst, const void* src) {
    asm volatile("cp.async.cg.shared.global [%0], [%1], 16;" :: "r"(dst), "l"(src) : "memory");
}
__device__ __forceinline__ void cp_commit() { asm volatile("cp.async.commit_group;" ::: "memory"); }
__device__ __forceinline__ void cp_wait0()  { asm volatile("cp.async.wait_group 0;" ::: "memory"); }

__device__ __forceinline__ void ldsm4(uint32_t* r, uint32_t addr) {
    asm volatile("ldmatrix.sync.aligned.m8n8.x4.shared.b16 {%0,%1,%2,%3}, [%4];"
        : "=r"(r[0]), "=r"(r[1]), "=r"(r[2]), "=r"(r[3]) : "r"(addr));
}
// s8 x s8 -> s32 accumulate, m16n8k32
__device__ __forceinline__ void imma16832(int* c, const uint32_t* a, const uint32_t* b) {
    asm volatile(
        "mma.sync.aligned.m16n8k32.row.col.s32.s8.s8.s32 "
        "{%0,%1,%2,%3}, {%4,%5,%6,%7}, {%8,%9}, {%0,%1,%2,%3};"
        : "+r"(c[0]), "+r"(c[1]), "+r"(c[2]), "+r"(c[3])
        : "r"(a[0]), "r"(a[1]), "r"(a[2]), "r"(a[3]), "r"(b[0]), "r"(b[1]));
}

// ============================================================
// K0: zero scratch accumulators
// ============================================================
__global__ __launch_bounds__(256) void k_init() {
    int gid = blockIdx.x * blockDim.x + threadIdx.x;
    int stride = gridDim.x * blockDim.x;
    for (int i = gid; i < KC * DIM; i += stride) g_dw[i] = 0.0f;
    if (gid < KC) g_counts[gid] = 0.0f;
    if (gid == 0) { g_loss_sum = 0.0f; g_n_sum = 0.0f; g_plogp_sum = 0.0f; }
}

// ============================================================
// K1: fp32 -> int8 (scale 16, saturate), row-major
// ============================================================
__global__ __launch_bounds__(256) void k_conv8(const float* __restrict__ src,
                                               int8_t* __restrict__ dst, int n4) {
    int stride = gridDim.x * blockDim.x;
    for (int g = blockIdx.x * blockDim.x + threadIdx.x; g < n4; g += stride) {
        float4 v = *(const float4*)(src + (size_t)g * 4);
        int q0 = max(-127, min(127, __float2int_rn(v.x * QSCALE)));
        int q1 = max(-127, min(127, __float2int_rn(v.y * QSCALE)));
        int q2 = max(-127, min(127, __float2int_rn(v.z * QSCALE)));
        int q3 = max(-127, min(127, __float2int_rn(v.w * QSCALE)));
        uint32_t packed = (uint32_t)(q0 & 0xff) | ((uint32_t)(q1 & 0xff) << 8)
                        | ((uint32_t)(q2 & 0xff) << 16) | ((uint32_t)(q3 & 0xff) << 24);
        ((uint32_t*)dst)[g] = packed;
    }
}

// ============================================================
// K2: ||e_k||^2 (fp32, one warp per code row)
// ============================================================
__global__ __launch_bounds__(256) void k_enorm2(const float* __restrict__ E) {
    int warp = (blockIdx.x * blockDim.x + threadIdx.x) >> 5;
    int lane = threadIdx.x & 31;
    if (warp >= KC) return;
    const float* row = E + (size_t)warp * DIM;
    float s = 0.0f;
    #pragma unroll
    for (int d = lane * 4; d < DIM; d += 32 * 4) {
        float4 v = *(const float4*)(row + d);
        s = fmaf(v.x, v.x, s); s = fmaf(v.y, v.y, s);
        s = fmaf(v.z, v.z, s); s = fmaf(v.w, v.w, s);
    }
    #pragma unroll
    for (int o = 16; o; o >>= 1) s += __shfl_xor_sync(0xffffffffu, s, o);
    if (lane == 0) g_enorm2[warp] = s;
}

// ============================================================
// K3: int8 IMMA GEMM + per-thread top-3 candidates
// CTA tile: 128 rows x 128 cols per n-tile; 64 n-tiles; k-chunk=64.
// 8 warps as 4 (row) x 2 (col); warp tile 32x64; s32 accumulators.
// smem: double-buffered {A 128x64B, B 128x64B}, 80B row stride.
// top-3 per (thread, rowslot=4) in smem planes.
// 2 CTAs/SM -> grid 256 in one wave.
// ============================================================
#define TILE_A   10240                  // 128 * 80
#define BUF_B    20480                  // A + B
#define TOPV     (2 * BUF_B)            // float planes [3][4][256] = 12 KB
#define TOPI12   (TOPV + 12288)         // u32 plane [4][256]: i1<<16|i2 = 4 KB
#define TOPI3    (TOPI12 + 4096)        // u32 plane [4][256]: i3 = 4 KB
#define SMEM_MMA (TOPI3 + 4096)         // 61440

__device__ __forceinline__ void stage8(uint32_t sbuf, const int8_t* Ab, const int8_t* Bb,
                                       int c, int tid) {
    #pragma unroll
    for (int i = 0; i < 2; ++i) {       // A: 512 x 16B segs
        int s = tid + i * 256;
        int r = s >> 2, cs = s & 3;
        cp16(sbuf + r * 80 + cs * 16, Ab + (size_t)r * DIM + c * 64 + cs * 16);
    }
    #pragma unroll
    for (int i = 0; i < 2; ++i) {       // B: 512 x 16B segs
        int s = tid + i * 256;
        int r = s >> 2, cs = s & 3;
        cp16(sbuf + TILE_A + r * 80 + cs * 16, Bb + (size_t)r * DIM + c * 64 + cs * 16);
    }
}

__global__ __launch_bounds__(256, 2) void k_argmin_mma() {
    extern __shared__ char smem[];
    const uint32_t sb = smem_u32(smem);
    const int tid = threadIdx.x;
    const int lane = tid & 31;
    const int wid = tid >> 5;
    const int wr = wid >> 1;            // 0..3 : 32-row band
    const int wc = wid & 1;             // 0..1 : 64-col band
    const int mt = blockIdx.x;

    const int8_t* Ab = g_xs8 + (size_t)mt * 128 * DIM;

    const uint32_t offA = (uint32_t)((wr * 32 + (lane & 15)) * 80 + (lane >> 4) * 16);
    const uint32_t offB = (uint32_t)(TILE_A + (wc * 64 + (lane & 7) + ((lane >> 4) & 1) * 8) * 80
                                     + ((lane >> 3) & 1) * 16);

    float* vp = (float*)(smem + TOPV);
    uint32_t* ip12 = (uint32_t*)(smem + TOPI12);
    uint32_t* ip3  = (uint32_t*)(smem + TOPI3);
    #pragma unroll
    for (int j = 0; j < 3; ++j)
        #pragma unroll
        for (int s = 0; s < 4; ++s) vp[(j * 4 + s) * 256 + tid] = FLT_MAX;
    #pragma unroll
    for (int s = 0; s < 4; ++s) { ip12[s * 256 + tid] = 0; ip3[s * 256 + tid] = 0; }

    #pragma unroll 1
    for (int t = 0; t < KC / 128; ++t) {
        const int8_t* Bb = g_es8 + (size_t)t * 128 * DIM;
        int acc[2][8][4];
        #pragma unroll
        for (int m = 0; m < 2; ++m)
            #pragma unroll
            for (int n = 0; n < 8; ++n)
                #pragma unroll
                for (int r = 0; r < 4; ++r) acc[m][n][r] = 0;

        stage8(sb, Ab, Bb, 0, tid);
        cp_commit();

        #pragma unroll 1
        for (int c = 0; c < 8; ++c) {
            cp_wait0();
            __syncthreads();
            if (c + 1 < 8) {
                stage8(sb + ((c + 1) & 1) * BUF_B, Ab, Bb, c + 1, tid);
                cp_commit();
            }
            const uint32_t buf = sb + (c & 1) * BUF_B;
            #pragma unroll
            for (int ks = 0; ks < 2; ++ks) {
                uint32_t aF[2][4], bF[4][4];
                #pragma unroll
                for (int m = 0; m < 2; ++m)
                    ldsm4(aF[m], buf + offA + m * (16 * 80) + ks * 32);
                #pragma unroll
                for (int p = 0; p < 4; ++p)
                    ldsm4(bF[p], buf + offB + p * (16 * 80) + ks * 32);
                #pragma unroll
                for (int m = 0; m < 2; ++m)
                    #pragma unroll
                    for (int p = 0; p < 4; ++p) {
                        imma16832(acc[m][p * 2],     aF[m], &bF[p][0]);
                        imma16832(acc[m][p * 2 + 1], aF[m], &bF[p][2]);
                    }
            }
            // NOTE: no trailing sync — next iteration's top barrier covers reuse
        }

        // fold tile into per-slot top-3
        #pragma unroll
        for (int m = 0; m < 2; ++m)
            #pragma unroll
            for (int h = 0; h < 2; ++h) {
                const int slot = m * 2 + h;
                float v1 = vp[(0 * 4 + slot) * 256 + tid];
                float v2 = vp[(1 * 4 + slot) * 256 + tid];
                float v3 = vp[(2 * 4 + slot) * 256 + tid];
                uint32_t p12 = ip12[slot * 256 + tid];
                uint32_t p3  = ip3[slot * 256 + tid];
                int i1 = p12 >> 16, i2 = p12 & 0xffff, i3 = (int)p3;
                #pragma unroll
                for (int f = 0; f < 8; ++f) {
                    const int colb = t * 128 + wc * 64 + (f >> 1) * 16 + (f & 1) * 8
                                     + 2 * (lane & 3);
                    #pragma unroll
                    for (int q = 0; q < 2; ++q) {
                        const int col = colb + q;
                        float s = fmaf(-0.0078125f, (float)acc[m][f][h * 2 + q],
                                       __ldg(&g_enorm2[col]));
                        if (s < v1)      { v3 = v2; i3 = i2; v2 = v1; i2 = i1; v1 = s; i1 = col; }
                        else if (s < v2) { v3 = v2; i3 = i2; v2 = s; i2 = col; }
                        else if (s < v3) { v3 = s; i3 = col; }
                    }
                }
                vp[(0 * 4 + slot) * 256 + tid] = v1;
                vp[(1 * 4 + slot) * 256 + tid] = v2;
                vp[(2 * 4 + slot) * 256 + tid] = v3;
                ip12[slot * 256 + tid] = (uint32_t)(i1 << 16) | (uint32_t)i2;
                ip3[slot * 256 + tid]  = (uint32_t)i3;
            }
    }

    // dump candidates: key = (f16(approx) << 16) | col ; [row][24]
    __syncthreads();
    uint32_t* keys = (uint32_t*)smem;            // 128*24*4 = 12 KB (reuse buffers)
    #pragma unroll
    for (int m = 0; m < 2; ++m)
        #pragma unroll
        for (int h = 0; h < 2; ++h) {
            const int slot = m * 2 + h;
            float v1 = vp[(0 * 4 + slot) * 256 + tid];
            float v2 = vp[(1 * 4 + slot) * 256 + tid];
            float v3 = vp[(2 * 4 + slot) * 256 + tid];
            uint32_t p12 = ip12[slot * 256 + tid];
            uint32_t p3  = ip3[slot * 256 + tid];
            int row = wr * 32 + m * 16 + h * 8 + (lane >> 2);
            int ent = (wc * 4 + (lane & 3)) * 3;
            keys[row * 24 + ent + 0] =
                ((uint32_t)__half_as_ushort(__float2half_rn(v1)) << 16) | (p12 >> 16);
            keys[row * 24 + ent + 1] =
                ((uint32_t)__half_as_ushort(__float2half_rn(v2)) << 16) | (p12 & 0xffff);
            keys[row * 24 + ent + 2] =
                ((uint32_t)__half_as_ushort(__float2half_rn(v3)) << 16) | (p3 & 0xffff);
        }
    __syncthreads();
    #pragma unroll
    for (int j = 0; j < 12; ++j) {
        int lin = tid + j * 256;                 // 0..3071
        g_cand[(size_t)mt * (128 * NCAND) + lin] = keys[lin];
    }
}

// ============================================================
// K3b: fused threshold-gated exact re-rank + gather/loss/counts/dw
// block = 1 row, 128 threads.
// ============================================================
__global__ __launch_bounds__(128) void k_rerank(const float* __restrict__ X,
                                                const float* __restrict__ E,
                                                float* __restrict__ out) {
    __shared__ float xs[DIM];
    __shared__ unsigned int keys[32];
    __shared__ unsigned int mkey;
    __shared__ unsigned long long res;
    __shared__ float wsum[4];
    const int row = blockIdx.x;
    const int tid = threadIdx.x;
    const int lane = tid & 31;
    const int warp = tid >> 5;

    if (tid < 32) keys[tid] = (tid < NCAND) ? g_cand[(size_t)row * NCAND + tid] : 0xFFFFFFFFu;
    *(float4*)(xs + tid * 4) = *(const float4*)(X + (size_t)row * DIM + tid * 4);
    if (tid == 0) res = ~0ull;
    __syncthreads();

    if (tid < 32) {
        unsigned int m = __reduce_min_sync(0xffffffffu, keys[tid]);
        if (tid == 0) mkey = m;
    }
    __syncthreads();

    const float thresh = __half2float(__ushort_as_half((unsigned short)(mkey >> 16)))
                         + RERANK_THRESH;

    for (int c = warp; c < NCAND; c += 4) {
        unsigned int k = keys[c];
        float v = __half2float(__ushort_as_half((unsigned short)(k >> 16)));
        if (v <= thresh) {
            int col = (int)(k & 0xffffu);
            const float* er = E + (size_t)col * DIM;
            float dot = 0.0f;
            #pragma unroll
            for (int j = 0; j < 4; ++j) {
                float4 e = *(const float4*)(er + j * 128 + lane * 4);
                float4 x = *(const float4*)(xs + j * 128 + lane * 4);
                dot = fmaf(x.x, e.x, dot); dot = fmaf(x.y, e.y, dot);
                dot = fmaf(x.z, e.z, dot); dot = fmaf(x.w, e.w, dot);
            }
            #pragma unroll
            for (int o = 16; o; o >>= 1) dot += __shfl_xor_sync(0xffffffffu, dot, o);
            if (lane == 0) {
                float s = fmaf(-2.0f, dot, __ldg(&g_enorm2[col]));
                unsigned long long key64 =
                    ((unsigned long long)__float_as_uint(s) << 32) | (unsigned int)col;
                atomicMin(&res, key64);
            }
        }
    }
    __syncthreads();
    const int best = (int)(res & 0xffffffffull);

    // fused gather: quantized write, dw scatter, loss, counts
    const float* er = E + (size_t)best * DIM;
    float* dwr = g_dw + (size_t)best * DIM;
    int d = tid * 4;
    float4 q = *(const float4*)(er + d);
    float4 x = *(const float4*)(xs + d);
    *(float4*)(out + O_Q + (size_t)row * DIM + d) = q;
    atomicAdd(dwr + d + 0, x.x);
    atomicAdd(dwr + d + 1, x.y);
    atomicAdd(dwr + d + 2, x.z);
    atomicAdd(dwr + d + 3, x.w);

    float dx = q.x - x.x, dy = q.y - x.y, dz = q.z - x.z, dw = q.w - x.w;
    float ls = dx * dx + dy * dy + dz * dz + dw * dw;
    #pragma unroll
    for (int o = 16; o; o >>= 1) ls += __shfl_xor_sync(0xffffffffu, ls, o);
    if (lane == 0) wsum[warp] = ls;
    __syncthreads();
    if (tid == 0) {
        atomicAdd(&g_loss_sum, wsum[0] + wsum[1] + wsum[2] + wsum[3]);
        atomicAdd(&g_counts[best], 1.0f);
    }
}

// ============================================================
// K5a: EMA cluster-size pre + global sums
// ============================================================
__global__ __launch_bounds__(256) void k_stats1(const float* __restrict__ cs_in) {
    __shared__ float sn[8], sp[8];
    int k = blockIdx.x * 256 + threadIdx.x;
    float cnt = g_counts[k];
    float pre = fmaf(cs_in[k], DECAYF, OMDF * cnt);
    g_cs_pre[k] = pre;
    float p = cnt * (1.0f / (float)NROWS);
    float pl = p * logf(p + 1e-10f);
    float ns = pre, ps = pl;
    #pragma unroll
    for (int o = 16; o; o >>= 1) {
        ns += __shfl_xor_sync(0xffffffffu, ns, o);
        ps += __shfl_xor_sync(0xffffffffu, ps, o);
    }
    int lane = threadIdx.x & 31, warp = threadIdx.x >> 5;
    if (lane == 0) { sn[warp] = ns; sp[warp] = ps; }
    __syncthreads();
    if (threadIdx.x == 0) {
        float a = 0.0f, b = 0.0f;
        #pragma unroll
        for (int w = 0; w < 8; ++w) { a += sn[w]; b += sp[w]; }
        atomicAdd(&g_n_sum, a);
        atomicAdd(&g_plogp_sum, b);
    }
}

// ============================================================
// K5b: finalize new_cs + scalars
// ============================================================
__global__ __launch_bounds__(256) void k_stats2(float* __restrict__ out) {
    int k = blockIdx.x * 256 + threadIdx.x;
    float n = g_n_sum;
    float ncs = (g_cs_pre[k] + EPSF) / (n + (float)KC * EPSF) * n;
    out[O_CS + k] = ncs;
    if (blockIdx.x == 0 && threadIdx.x == 0) {
        out[O_LOSS] = 0.25f * (g_loss_sum / (float)(NROWS * DIM));
        out[O_PERP] = expf(-g_plogp_sum);
    }
}

// ============================================================
// K6: new_w + new_embedding (float2 stores: regions only 8B aligned)
// ============================================================
__global__ __launch_bounds__(256) void k_final(const float* __restrict__ ema_w,
                                               float* __restrict__ out) {
    const float* ncs = out + O_CS;
    int i = blockIdx.x * blockDim.x + threadIdx.x;
    int total = KC * DIM / 4;
    int stride = gridDim.x * blockDim.x;
    for (; i < total; i += stride) {
        int e = i * 4;
        int k = e >> 9;
        float4 w  = *(const float4*)(ema_w + e);
        float4 dv = *(const float4*)(g_dw + e);
        float4 nw;
        nw.x = fmaf(w.x, DECAYF, OMDF * dv.x);
        nw.y = fmaf(w.y, DECAYF, OMDF * dv.y);
        nw.z = fmaf(w.z, DECAYF, OMDF * dv.z);
        nw.w = fmaf(w.w, DECAYF, OMDF * dv.w);
        *(float2*)(out + O_W + e)     = make_float2(nw.x, nw.y);
        *(float2*)(out + O_W + e + 2) = make_float2(nw.z, nw.w);
        float inv = 1.0f / ncs[k];
        *(float2*)(out + O_EMB + e)     = make_float2(nw.x * inv, nw.y * inv);
        *(float2*)(out + O_EMB + e + 2) = make_float2(nw.z * inv, nw.w * inv);
    }
}

// ============================================================
extern "C" void kernel_launch(void* const* d_in, const int* in_sizes, int n_in,
                              void* d_out, int out_size) {
    const float* X     = (const float*)d_in[0];
    const float* E     = (const float*)d_in[1];
    const float* cs    = (const float*)d_in[2];
    const float* ema_w = (const float*)d_in[3];
    float* out = (float*)d_out;

    cudaFuncSetAttribute(k_argmin_mma, cudaFuncAttributeMaxDynamicSharedMemorySize, SMEM_MMA);

    int8_t *x8, *e8;
    cudaGetSymbolAddress((void**)&x8, g_xs8);
    cudaGetSymbolAddress((void**)&e8, g_es8);

    k_init  <<<4096, 256>>>();
    k_conv8 <<<2048, 256>>>(X, x8, NROWS * DIM / 4);
    k_conv8 <<<1024, 256>>>(E, e8, KC * DIM / 4);
    k_enorm2<<<KC / 8, 256>>>(E);
    k_argmin_mma<<<NROWS / 128, 256, SMEM_MMA>>>();
    k_rerank<<<NROWS, 128>>>(X, E, out);
    k_stats1<<<KC / 256, 256>>>(cs);
    k_stats2<<<KC / 256, 256>>>(out);
    k_final <<<2048, 256>>>(ema_w, out);
}

// round 9
// speedup vs baseline: 10.2998x; 1.1290x over previous
#include <cuda_runtime.h>
#include <cuda_fp16.h>
#include <math.h>
#include <float.h>
#include <stdint.h>

// Problem constants
#define NROWS 32768
#define KC    8192
#define DIM   512

#define DECAYF 0.99f
#define OMDF   0.01f
#define EPSF   1e-5f

#define NCAND 24              // 8 owner threads x top-3 per row
#define RERANK_THRESH 10.0f   // int8 distance err sigma ~1.2 -> 8.6 sigma gate
#define QSCALE 16.0f          // dot = acc/256 ; s = en - acc/128

// ============================================================
// scratch (device globals)
// ============================================================
__device__ float g_enorm2[KC];
__device__ unsigned int g_cand[NROWS * NCAND];
__device__ float g_counts[KC];
__device__ float g_dw[KC * DIM];
__device__ float g_cs_pre[KC];
__device__ float g_loss_sum;
__device__ float g_n_sum;
__device__ float g_plogp_sum;

// int8 operands, row-major [rows][512]
__device__ int8_t g_xs8[NROWS * DIM];
__device__ int8_t g_es8[KC * DIM];

// ---- output layout (O_EMB/O_W only 8-byte aligned -> float2 there) ----
#define O_Q    0
#define O_LOSS (NROWS * DIM)
#define O_PERP (O_LOSS + 1)
#define O_EMB  (O_PERP + 1)
#define O_CS   (O_EMB + KC * DIM)
#define O_W    (O_CS + KC)

// ============================================================
// PTX helpers (baseline compute_100 = sm_80+ features only)
// ============================================================
__device__ __forceinline__ uint32_t smem_u32(const void* p) {
    uint32_t a;
    asm("{ .reg .u64 t; cvta.to.shared.u64 t, %1; cvt.u32.u64 %0, t; }" : "=r"(a) : "l"(p));
    return a;
}
__device__ __forceinline__ void cp16(uint32_t dst, const void* src) {
    asm volatile("cp.async.cg.shared.global [%0], [%1], 16;" :: "r"(dst), "l"(src) : "memory");
}
__device__ __forceinline__ void cp_commit() { asm volatile("cp.async.commit_group;" ::: "memory"); }
__device__ __forceinline__ void cp_wait0()  { asm volatile("cp.async.wait_group 0;" ::: "memory"); }

__device__ __forceinline__ void ldsm4(uint32_t* r, uint32_t addr) {
    asm volatile("ldmatrix.sync.aligned.m8n8.x4.shared.b16 {%0,%1,%2,%3}, [%4];"
        : "=r"(r[0]), "=r"(r[1]), "=r"(r[2]), "=r"(r[3]) : "r"(addr));
}
__device__ __forceinline__ void imma16832(int* c, const uint32_t* a, const uint32_t* b) {
    asm volatile(
        "mma.sync.aligned.m16n8k32.row.col.s32.s8.s8.s32 "
        "{%0,%1,%2,%3}, {%4,%5,%6,%7}, {%8,%9}, {%0,%1,%2,%3};"
        : "+r"(c[0]), "+r"(c[1]), "+r"(c[2]), "+r"(c[3])
        : "r"(a[0]), "r"(a[1]), "r"(a[2]), "r"(a[3]), "r"(b[0]), "r"(b[1]));
}

// ============================================================
// K0: fused prep — convert X/E to int8, zero accumulators
// ============================================================
__device__ __forceinline__ uint32_t quant4(float4 v) {
    int q0 = max(-127, min(127, __float2int_rn(v.x * QSCALE)));
    int q1 = max(-127, min(127, __float2int_rn(v.y * QSCALE)));
    int q2 = max(-127, min(127, __float2int_rn(v.z * QSCALE)));
    int q3 = max(-127, min(127, __float2int_rn(v.w * QSCALE)));
    return (uint32_t)(q0 & 0xff) | ((uint32_t)(q1 & 0xff) << 8)
         | ((uint32_t)(q2 & 0xff) << 16) | ((uint32_t)(q3 & 0xff) << 24);
}

__global__ __launch_bounds__(256) void k_prep(const float* __restrict__ X,
                                              const float* __restrict__ E) {
    const int gid = blockIdx.x * blockDim.x + threadIdx.x;
    const int stride = gridDim.x * blockDim.x;
    const int n4x = NROWS * DIM / 4;
    const int n4e = KC * DIM / 4;
    for (int g = gid; g < n4x; g += stride)
        ((uint32_t*)g_xs8)[g] = quant4(*(const float4*)(X + (size_t)g * 4));
    for (int g = gid; g < n4e; g += stride)
        ((uint32_t*)g_es8)[g] = quant4(*(const float4*)(E + (size_t)g * 4));
    for (int i = gid; i < KC * DIM / 4; i += stride)
        *(float4*)(g_dw + (size_t)i * 4) = make_float4(0.f, 0.f, 0.f, 0.f);
    if (gid < KC) g_counts[gid] = 0.0f;
    if (gid == 0) { g_loss_sum = 0.0f; g_n_sum = 0.0f; g_plogp_sum = 0.0f; }
}

// ============================================================
// K2: ||e_k||^2 (fp32, one warp per code row)
// ============================================================
__global__ __launch_bounds__(256) void k_enorm2(const float* __restrict__ E) {
    int warp = (blockIdx.x * blockDim.x + threadIdx.x) >> 5;
    int lane = threadIdx.x & 31;
    if (warp >= KC) return;
    const float* row = E + (size_t)warp * DIM;
    float s = 0.0f;
    #pragma unroll
    for (int d = lane * 4; d < DIM; d += 32 * 4) {
        float4 v = *(const float4*)(row + d);
        s = fmaf(v.x, v.x, s); s = fmaf(v.y, v.y, s);
        s = fmaf(v.z, v.z, s); s = fmaf(v.w, v.w, s);
    }
    #pragma unroll
    for (int o = 16; o; o >>= 1) s += __shfl_xor_sync(0xffffffffu, s, o);
    if (lane == 0) g_enorm2[warp] = s;
}

// ============================================================
// K3: int8 IMMA GEMM, A tile RESIDENT in smem.
// CTA: 128 rows (A resident, 128x512 s8, 528B row stride) x
//      64 n-tiles of 128 codes (B double-buffered, 80B stride).
// 8 warps as 4 (row) x 2 (col); warp tile 32x64; s32 acc.
// smem: A 67584 + B 2x10240 + top3 20480 = 108544.
// ============================================================
#define SM_A     0
#define A_STRIDE 528
#define A_BYTES  (128 * A_STRIDE)          // 67584
#define SM_B     A_BYTES
#define TILE_BB  10240                     // 128 * 80
#define TOPV     (SM_B + 2 * TILE_BB)      // float planes [3][4][256] = 12 KB
#define TOPI12   (TOPV + 12288)
#define TOPI3    (TOPI12 + 4096)
#define SMEM_MMA (TOPI3 + 4096)            // 108544

__global__ __launch_bounds__(256, 2) void k_argmin_mma() {
    extern __shared__ char smem[];
    const uint32_t sb = smem_u32(smem);
    const int tid = threadIdx.x;
    const int lane = tid & 31;
    const int wid = tid >> 5;
    const int wr = wid >> 1;            // 0..3 : 32-row band
    const int wc = wid & 1;             // 0..1 : 64-col band
    const int mt = blockIdx.x;

    // ---- stage A resident: 128 rows x 512B, 4096 x 16B segs ----
    {
        const int8_t* Ab = g_xs8 + (size_t)mt * 128 * DIM;
        #pragma unroll
        for (int i = 0; i < 16; ++i) {
            int seg = tid + i * 256;
            int r = seg >> 5, cs = seg & 31;
            cp16(sb + SM_A + r * A_STRIDE + cs * 16, Ab + (size_t)r * DIM + cs * 16);
        }
        cp_commit();
    }

    // FIX vs R8: ldmatrix addresses MUST include the smem base sb.
    const uint32_t offA = sb + (uint32_t)(SM_A + (wr * 32 + (lane & 15)) * A_STRIDE
                                          + (lane >> 4) * 16);
    const uint32_t offB = sb + (uint32_t)(SM_B + (wc * 64 + (lane & 7) + ((lane >> 4) & 1) * 8) * 80
                                          + ((lane >> 3) & 1) * 16);

    float* vp = (float*)(smem + TOPV);
    uint32_t* ip12 = (uint32_t*)(smem + TOPI12);
    uint32_t* ip3  = (uint32_t*)(smem + TOPI3);
    #pragma unroll
    for (int j = 0; j < 3; ++j)
        #pragma unroll
        for (int s = 0; s < 4; ++s) vp[(j * 4 + s) * 256 + tid] = FLT_MAX;
    #pragma unroll
    for (int s = 0; s < 4; ++s) { ip12[s * 256 + tid] = 0; ip3[s * 256 + tid] = 0; }

    // stage B chunk 0 of tile 0
    {
        const int8_t* Bb = g_es8;
        #pragma unroll
        for (int i = 0; i < 2; ++i) {
            int seg = tid + i * 256;
            int r = seg >> 2, cs = seg & 3;
            cp16(sb + SM_B + r * 80 + cs * 16, Bb + (size_t)r * DIM + cs * 16);
        }
        cp_commit();
    }

    #pragma unroll 1
    for (int t = 0; t < KC / 128; ++t) {
        const int8_t* Bb = g_es8 + (size_t)t * 128 * DIM;
        int acc[2][8][4];
        #pragma unroll
        for (int m = 0; m < 2; ++m)
            #pragma unroll
            for (int n = 0; n < 8; ++n)
                #pragma unroll
                for (int r = 0; r < 4; ++r) acc[m][n][r] = 0;

        #pragma unroll 1
        for (int c = 0; c < 8; ++c) {
            cp_wait0();
            __syncthreads();
            // stage next B chunk (possibly first chunk of next tile)
            if (c + 1 < 8 || t + 1 < KC / 128) {
                const int8_t* Bn = (c + 1 < 8) ? Bb : (g_es8 + (size_t)(t + 1) * 128 * DIM);
                const int cn = (c + 1) & 7;
                const uint32_t bdst = sb + SM_B + ((c + 1) & 1) * TILE_BB;
                #pragma unroll
                for (int i = 0; i < 2; ++i) {
                    int seg = tid + i * 256;
                    int r = seg >> 2, cs = seg & 3;
                    cp16(bdst + r * 80 + cs * 16, Bn + (size_t)r * DIM + cn * 64 + cs * 16);
                }
                cp_commit();
            }
            const uint32_t bbuf = (uint32_t)((c & 1) * TILE_BB);
            const uint32_t abase = offA + c * 64;
            #pragma unroll
            for (int ks = 0; ks < 2; ++ks) {
                uint32_t aF[2][4], bF[4][4];
                #pragma unroll
                for (int m = 0; m < 2; ++m)
                    ldsm4(aF[m], abase + m * (16 * A_STRIDE) + ks * 32);
                #pragma unroll
                for (int p = 0; p < 4; ++p)
                    ldsm4(bF[p], offB + bbuf + p * (16 * 80) + ks * 32);
                #pragma unroll
                for (int m = 0; m < 2; ++m)
                    #pragma unroll
                    for (int p = 0; p < 4; ++p) {
                        imma16832(acc[m][p * 2],     aF[m], &bF[p][0]);
                        imma16832(acc[m][p * 2 + 1], aF[m], &bF[p][2]);
                    }
            }
        }

        // fold tile into per-slot top-3
        #pragma unroll
        for (int m = 0; m < 2; ++m)
            #pragma unroll
            for (int h = 0; h < 2; ++h) {
                const int slot = m * 2 + h;
                float v1 = vp[(0 * 4 + slot) * 256 + tid];
                float v2 = vp[(1 * 4 + slot) * 256 + tid];
                float v3 = vp[(2 * 4 + slot) * 256 + tid];
                uint32_t p12 = ip12[slot * 256 + tid];
                uint32_t p3  = ip3[slot * 256 + tid];
                int i1 = p12 >> 16, i2 = p12 & 0xffff, i3 = (int)p3;
                #pragma unroll
                for (int f = 0; f < 8; ++f) {
                    const int colb = t * 128 + wc * 64 + (f >> 1) * 16 + (f & 1) * 8
                                     + 2 * (lane & 3);
                    #pragma unroll
                    for (int q = 0; q < 2; ++q) {
                        const int col = colb + q;
                        float s = fmaf(-0.0078125f, (float)acc[m][f][h * 2 + q],
                                       __ldg(&g_enorm2[col]));
                        if (s < v1)      { v3 = v2; i3 = i2; v2 = v1; i2 = i1; v1 = s; i1 = col; }
                        else if (s < v2) { v3 = v2; i3 = i2; v2 = s; i2 = col; }
                        else if (s < v3) { v3 = s; i3 = col; }
                    }
                }
                vp[(0 * 4 + slot) * 256 + tid] = v1;
                vp[(1 * 4 + slot) * 256 + tid] = v2;
                vp[(2 * 4 + slot) * 256 + tid] = v3;
                ip12[slot * 256 + tid] = (uint32_t)(i1 << 16) | (uint32_t)i2;
                ip3[slot * 256 + tid]  = (uint32_t)i3;
            }
    }

    // dump candidates: key = (f16(approx) << 16) | col ; [row][24]
    __syncthreads();
    uint32_t* keys = (uint32_t*)smem;            // reuse A region, 12 KB
    #pragma unroll
    for (int m = 0; m < 2; ++m)
        #pragma unroll
        for (int h = 0; h < 2; ++h) {
            const int slot = m * 2 + h;
            float v1 = vp[(0 * 4 + slot) * 256 + tid];
            float v2 = vp[(1 * 4 + slot) * 256 + tid];
            float v3 = vp[(2 * 4 + slot) * 256 + tid];
            uint32_t p12 = ip12[slot * 256 + tid];
            uint32_t p3  = ip3[slot * 256 + tid];
            int row = wr * 32 + m * 16 + h * 8 + (lane >> 2);
            int ent = (wc * 4 + (lane & 3)) * 3;
            keys[row * 24 + ent + 0] =
                ((uint32_t)__half_as_ushort(__float2half_rn(v1)) << 16) | (p12 >> 16);
            keys[row * 24 + ent + 1] =
                ((uint32_t)__half_as_ushort(__float2half_rn(v2)) << 16) | (p12 & 0xffff);
            keys[row * 24 + ent + 2] =
                ((uint32_t)__half_as_ushort(__float2half_rn(v3)) << 16) | (p3 & 0xffff);
        }
    __syncthreads();
    #pragma unroll
    for (int j = 0; j < 12; ++j) {
        int lin = tid + j * 256;                 // 0..3071
        g_cand[(size_t)mt * (128 * NCAND) + lin] = keys[lin];
    }
}

// ============================================================
// K3b: fused threshold-gated exact re-rank + gather/loss/counts/dw
// ============================================================
__global__ __launch_bounds__(128) void k_rerank(const float* __restrict__ X,
                                                const float* __restrict__ E,
                                                float* __restrict__ out) {
    __shared__ float xs[DIM];
    __shared__ unsigned int keys[32];
    __shared__ unsigned int mkey;
    __shared__ unsigned long long res;
    __shared__ float wsum[4];
    const int row = blockIdx.x;
    const int tid = threadIdx.x;
    const int lane = tid & 31;
    const int warp = tid >> 5;

    if (tid < 32) keys[tid] = (tid < NCAND) ? g_cand[(size_t)row * NCAND + tid] : 0xFFFFFFFFu;
    *(float4*)(xs + tid * 4) = *(const float4*)(X + (size_t)row * DIM + tid * 4);
    if (tid == 0) res = ~0ull;
    __syncthreads();

    if (tid < 32) {
        unsigned int m = __reduce_min_sync(0xffffffffu, keys[tid]);
        if (tid == 0) mkey = m;
    }
    __syncthreads();

    const float thresh = __half2float(__ushort_as_half((unsigned short)(mkey >> 16)))
                         + RERANK_THRESH;

    for (int c = warp; c < NCAND; c += 4) {
        unsigned int k = keys[c];
        float v = __half2float(__ushort_as_half((unsigned short)(k >> 16)));
        if (v <= thresh) {
            int col = (int)(k & 0xffffu);
            const float* er = E + (size_t)col * DIM;
            float dot = 0.0f;
            #pragma unroll
            for (int j = 0; j < 4; ++j) {
                float4 e = *(const float4*)(er + j * 128 + lane * 4);
                float4 x = *(const float4*)(xs + j * 128 + lane * 4);
                dot = fmaf(x.x, e.x, dot); dot = fmaf(x.y, e.y, dot);
                dot = fmaf(x.z, e.z, dot); dot = fmaf(x.w, e.w, dot);
            }
            #pragma unroll
            for (int o = 16; o; o >>= 1) dot += __shfl_xor_sync(0xffffffffu, dot, o);
            if (lane == 0) {
                float s = fmaf(-2.0f, dot, __ldg(&g_enorm2[col]));
                unsigned long long key64 =
                    ((unsigned long long)__float_as_uint(s) << 32) | (unsigned int)col;
                atomicMin(&res, key64);
            }
        }
    }
    __syncthreads();
    const int best = (int)(res & 0xffffffffull);

    const float* er = E + (size_t)best * DIM;
    float* dwr = g_dw + (size_t)best * DIM;
    int d = tid * 4;
    float4 q = *(const float4*)(er + d);
    float4 x = *(const float4*)(xs + d);
    *(float4*)(out + O_Q + (size_t)row * DIM + d) = q;
    atomicAdd(dwr + d + 0, x.x);
    atomicAdd(dwr + d + 1, x.y);
    atomicAdd(dwr + d + 2, x.z);
    atomicAdd(dwr + d + 3, x.w);

    float dx = q.x - x.x, dy = q.y - x.y, dz = q.z - x.z, dw = q.w - x.w;
    float ls = dx * dx + dy * dy + dz * dz + dw * dw;
    #pragma unroll
    for (int o = 16; o; o >>= 1) ls += __shfl_xor_sync(0xffffffffu, ls, o);
    if (lane == 0) wsum[warp] = ls;
    __syncthreads();
    if (tid == 0) {
        atomicAdd(&g_loss_sum, wsum[0] + wsum[1] + wsum[2] + wsum[3]);
        atomicAdd(&g_counts[best], 1.0f);
    }
}

// ============================================================
// K5a/K5b/K6: EMA stats + finalize (unchanged, verified)
// ============================================================
__global__ __launch_bounds__(256) void k_stats1(const float* __restrict__ cs_in) {
    __shared__ float sn[8], sp[8];
    int k = blockIdx.x * 256 + threadIdx.x;
    float cnt = g_counts[k];
    float pre = fmaf(cs_in[k], DECAYF, OMDF * cnt);
    g_cs_pre[k] = pre;
    float p = cnt * (1.0f / (float)NROWS);
    float pl = p * logf(p + 1e-10f);
    float ns = pre, ps = pl;
    #pragma unroll
    for (int o = 16; o; o >>= 1) {
        ns += __shfl_xor_sync(0xffffffffu, ns, o);
        ps += __shfl_xor_sync(0xffffffffu, ps, o);
    }
    int lane = threadIdx.x & 31, warp = threadIdx.x >> 5;
    if (lane == 0) { sn[warp] = ns; sp[warp] = ps; }
    __syncthreads();
    if (threadIdx.x == 0) {
        float a = 0.0f, b = 0.0f;
        #pragma unroll
        for (int w = 0; w < 8; ++w) { a += sn[w]; b += sp[w]; }
        atomicAdd(&g_n_sum, a);
        atomicAdd(&g_plogp_sum, b);
    }
}

__global__ __launch_bounds__(256) void k_stats2(float* __restrict__ out) {
    int k = blockIdx.x * 256 + threadIdx.x;
    float n = g_n_sum;
    float ncs = (g_cs_pre[k] + EPSF) / (n + (float)KC * EPSF) * n;
    out[O_CS + k] = ncs;
    if (blockIdx.x == 0 && threadIdx.x == 0) {
        out[O_LOSS] = 0.25f * (g_loss_sum / (float)(NROWS * DIM));
        out[O_PERP] = expf(-g_plogp_sum);
    }
}

__global__ __launch_bounds__(256) void k_final(const float* __restrict__ ema_w,
                                               float* __restrict__ out) {
    const float* ncs = out + O_CS;
    int i = blockIdx.x * blockDim.x + threadIdx.x;
    int total = KC * DIM / 4;
    int stride = gridDim.x * blockDim.x;
    for (; i < total; i += stride) {
        int e = i * 4;
        int k = e >> 9;
        float4 w  = *(const float4*)(ema_w + e);
        float4 dv = *(const float4*)(g_dw + e);
        float4 nw;
        nw.x = fmaf(w.x, DECAYF, OMDF * dv.x);
        nw.y = fmaf(w.y, DECAYF, OMDF * dv.y);
        nw.z = fmaf(w.z, DECAYF, OMDF * dv.z);
        nw.w = fmaf(w.w, DECAYF, OMDF * dv.w);
        *(float2*)(out + O_W + e)     = make_float2(nw.x, nw.y);
        *(float2*)(out + O_W + e + 2) = make_float2(nw.z, nw.w);
        float inv = 1.0f / ncs[k];
        *(float2*)(out + O_EMB + e)     = make_float2(nw.x * inv, nw.y * inv);
        *(float2*)(out + O_EMB + e + 2) = make_float2(nw.z * inv, nw.w * inv);
    }
}

// ============================================================
extern "C" void kernel_launch(void* const* d_in, const int* in_sizes, int n_in,
                              void* d_out, int out_size) {
    const float* X     = (const float*)d_in[0];
    const float* E     = (const float*)d_in[1];
    const float* cs    = (const float*)d_in[2];
    const float* ema_w = (const float*)d_in[3];
    float* out = (float*)d_out;

    cudaFuncSetAttribute(k_argmin_mma, cudaFuncAttributeMaxDynamicSharedMemorySize, SMEM_MMA);

    k_prep  <<<4096, 256>>>(X, E);
    k_enorm2<<<KC / 8, 256>>>(E);
    k_argmin_mma<<<NROWS / 128, 256, SMEM_MMA>>>();
    k_rerank<<<NROWS, 128>>>(X, E, out);
    k_stats1<<<KC / 256, 256>>>(cs);
    k_stats2<<<KC / 256, 256>>>(out);
    k_final <<<2048, 256>>>(ema_w, out);
}

// round 10
// speedup vs baseline: 11.2685x; 1.0940x over previous
#include <cuda_runtime.h>
#include <cuda_fp16.h>
#include <math.h>
#include <float.h>
#include <stdint.h>
#include <limits.h>

// Problem constants
#define NROWS 32768
#define KC    8192
#define DIM   512

#define DECAYF 0.99f
#define OMDF   0.01f
#define EPSF   1e-5f

#define NCAND 24              // 8 owner threads x top-3 per row
#define RERANK_THRESH 10.0f   // int8 distance err sigma ~1.2 -> 8.6 sigma gate
#define QSCALE 16.0f          // acc = 256*(x.e)_q ; s*128 = en*128 - acc

// ============================================================
// scratch (device globals)
// ============================================================
__device__ float g_enorm2[KC];
__device__ int   g_enorm2i[KC];       // round(128 * ||e||^2)
__device__ unsigned int g_cand[NROWS * NCAND];
__device__ float g_counts[KC];
__device__ float g_dw[KC * DIM];
__device__ float g_cs_pre[KC];
__device__ float g_loss_sum;
__device__ float g_n_sum;
__device__ float g_plogp_sum;

// int8 operands, row-major [rows][512]
__device__ int8_t g_xs8[NROWS * DIM];
__device__ int8_t g_es8[KC * DIM];

// ---- output layout (O_EMB/O_W only 8-byte aligned -> float2 there) ----
#define O_Q    0
#define O_LOSS (NROWS * DIM)
#define O_PERP (O_LOSS + 1)
#define O_EMB  (O_PERP + 1)
#define O_CS   (O_EMB + KC * DIM)
#define O_W    (O_CS + KC)

// ============================================================
// PTX helpers (baseline compute_100 = sm_80+ features only)
// ============================================================
__device__ __forceinline__ uint32_t smem_u32(const void* p) {
    uint32_t a;
    asm("{ .reg .u64 t; cvta.to.shared.u64 t, %1; cvt.u32.u64 %0, t; }" : "=r"(a) : "l"(p));
    return a;
}
__device__ __forceinline__ void cp16(uint32_t dst, const void* src) {
    asm volatile("cp.async.cg.shared.global [%0], [%1], 16;" :: "r"(dst), "l"(src) : "memory");
}
__device__ __forceinline__ void cp_commit() { asm volatile("cp.async.commit_group;" ::: "memory"); }
__device__ __forceinline__ void cp_wait0()  { asm volatile("cp.async.wait_group 0;" ::: "memory"); }

__device__ __forceinline__ void ldsm4(uint32_t* r, uint32_t addr) {
    asm volatile("ldmatrix.sync.aligned.m8n8.x4.shared.b16 {%0,%1,%2,%3}, [%4];"
        : "=r"(r[0]), "=r"(r[1]), "=r"(r[2]), "=r"(r[3]) : "r"(addr));
}
__device__ __forceinline__ void imma16832(int* c, const uint32_t* a, const uint32_t* b) {
    asm volatile(
        "mma.sync.aligned.m16n8k32.row.col.s32.s8.s8.s32 "
        "{%0,%1,%2,%3}, {%4,%5,%6,%7}, {%8,%9}, {%0,%1,%2,%3};"
        : "+r"(c[0]), "+r"(c[1]), "+r"(c[2]), "+r"(c[3])
        : "r"(a[0]), "r"(a[1]), "r"(a[2]), "r"(a[3]), "r"(b[0]), "r"(b[1]));
}

// ============================================================
// K0: fused prep — convert X/E to int8, zero accumulators
// ============================================================
__device__ __forceinline__ uint32_t quant4(float4 v) {
    int q0 = max(-127, min(127, __float2int_rn(v.x * QSCALE)));
    int q1 = max(-127, min(127, __float2int_rn(v.y * QSCALE)));
    int q2 = max(-127, min(127, __float2int_rn(v.z * QSCALE)));
    int q3 = max(-127, min(127, __float2int_rn(v.w * QSCALE)));
    return (uint32_t)(q0 & 0xff) | ((uint32_t)(q1 & 0xff) << 8)
         | ((uint32_t)(q2 & 0xff) << 16) | ((uint32_t)(q3 & 0xff) << 24);
}

__global__ __launch_bounds__(256) void k_prep(const float* __restrict__ X,
                                              const float* __restrict__ E) {
    const int gid = blockIdx.x * blockDim.x + threadIdx.x;
    const int stride = gridDim.x * blockDim.x;
    const int n4x = NROWS * DIM / 4;
    const int n4e = KC * DIM / 4;
    for (int g = gid; g < n4x; g += stride)
        ((uint32_t*)g_xs8)[g] = quant4(*(const float4*)(X + (size_t)g * 4));
    for (int g = gid; g < n4e; g += stride)
        ((uint32_t*)g_es8)[g] = quant4(*(const float4*)(E + (size_t)g * 4));
    for (int i = gid; i < KC * DIM / 4; i += stride)
        *(float4*)(g_dw + (size_t)i * 4) = make_float4(0.f, 0.f, 0.f, 0.f);
    if (gid < KC) g_counts[gid] = 0.0f;
    if (gid == 0) { g_loss_sum = 0.0f; g_n_sum = 0.0f; g_plogp_sum = 0.0f; }
}

// ============================================================
// K2: ||e_k||^2 (fp32 + int*128 variants, one warp per code row)
// ============================================================
__global__ __launch_bounds__(256) void k_enorm2(const float* __restrict__ E) {
    int warp = (blockIdx.x * blockDim.x + threadIdx.x) >> 5;
    int lane = threadIdx.x & 31;
    if (warp >= KC) return;
    const float* row = E + (size_t)warp * DIM;
    float s = 0.0f;
    #pragma unroll
    for (int d = lane * 4; d < DIM; d += 32 * 4) {
        float4 v = *(const float4*)(row + d);
        s = fmaf(v.x, v.x, s); s = fmaf(v.y, v.y, s);
        s = fmaf(v.z, v.z, s); s = fmaf(v.w, v.w, s);
    }
    #pragma unroll
    for (int o = 16; o; o >>= 1) s += __shfl_xor_sync(0xffffffffu, s, o);
    if (lane == 0) {
        g_enorm2[warp] = s;
        g_enorm2i[warp] = __float2int_rn(s * 128.0f);
    }
}

// ============================================================
// K3: int8 IMMA GEMM, A resident, INTEGER-domain top-3 fold.
// ============================================================
#define SM_A     0
#define A_STRIDE 528
#define A_BYTES  (128 * A_STRIDE)          // 67584
#define SM_B     A_BYTES
#define TILE_BB  10240                     // 128 * 80
#define TOPV     (SM_B + 2 * TILE_BB)      // int planes [3][4][256] = 12 KB
#define TOPI12   (TOPV + 12288)
#define TOPI3    (TOPI12 + 4096)
#define SMEM_MMA (TOPI3 + 4096)            // 108544

__global__ __launch_bounds__(256, 2) void k_argmin_mma() {
    extern __shared__ char smem[];
    const uint32_t sb = smem_u32(smem);
    const int tid = threadIdx.x;
    const int lane = tid & 31;
    const int wid = tid >> 5;
    const int wr = wid >> 1;            // 0..3 : 32-row band
    const int wc = wid & 1;             // 0..1 : 64-col band
    const int mt = blockIdx.x;

    // ---- stage A resident ----
    {
        const int8_t* Ab = g_xs8 + (size_t)mt * 128 * DIM;
        #pragma unroll
        for (int i = 0; i < 16; ++i) {
            int seg = tid + i * 256;
            int r = seg >> 5, cs = seg & 31;
            cp16(sb + SM_A + r * A_STRIDE + cs * 16, Ab + (size_t)r * DIM + cs * 16);
        }
        cp_commit();
    }

    const uint32_t offA = sb + (uint32_t)(SM_A + (wr * 32 + (lane & 15)) * A_STRIDE
                                          + (lane >> 4) * 16);
    const uint32_t offB = sb + (uint32_t)(SM_B + (wc * 64 + (lane & 7) + ((lane >> 4) & 1) * 8) * 80
                                          + ((lane >> 3) & 1) * 16);

    int* vp = (int*)(smem + TOPV);
    uint32_t* ip12 = (uint32_t*)(smem + TOPI12);
    uint32_t* ip3  = (uint32_t*)(smem + TOPI3);
    #pragma unroll
    for (int j = 0; j < 3; ++j)
        #pragma unroll
        for (int s = 0; s < 4; ++s) vp[(j * 4 + s) * 256 + tid] = INT_MAX;
    #pragma unroll
    for (int s = 0; s < 4; ++s) { ip12[s * 256 + tid] = 0; ip3[s * 256 + tid] = 0; }

    // stage B chunk 0 of tile 0
    {
        const int8_t* Bb = g_es8;
        #pragma unroll
        for (int i = 0; i < 2; ++i) {
            int seg = tid + i * 256;
            int r = seg >> 2, cs = seg & 3;
            cp16(sb + SM_B + r * 80 + cs * 16, Bb + (size_t)r * DIM + cs * 16);
        }
        cp_commit();
    }

    #pragma unroll 1
    for (int t = 0; t < KC / 128; ++t) {
        const int8_t* Bb = g_es8 + (size_t)t * 128 * DIM;
        int acc[2][8][4];
        #pragma unroll
        for (int m = 0; m < 2; ++m)
            #pragma unroll
            for (int n = 0; n < 8; ++n)
                #pragma unroll
                for (int r = 0; r < 4; ++r) acc[m][n][r] = 0;

        #pragma unroll 1
        for (int c = 0; c < 8; ++c) {
            cp_wait0();
            __syncthreads();
            if (c + 1 < 8 || t + 1 < KC / 128) {
                const int8_t* Bn = (c + 1 < 8) ? Bb : (g_es8 + (size_t)(t + 1) * 128 * DIM);
                const int cn = (c + 1) & 7;
                const uint32_t bdst = sb + SM_B + ((c + 1) & 1) * TILE_BB;
                #pragma unroll
                for (int i = 0; i < 2; ++i) {
                    int seg = tid + i * 256;
                    int r = seg >> 2, cs = seg & 3;
                    cp16(bdst + r * 80 + cs * 16, Bn + (size_t)r * DIM + cn * 64 + cs * 16);
                }
                cp_commit();
            }
            const uint32_t bbuf = (uint32_t)((c & 1) * TILE_BB);
            const uint32_t abase = offA + c * 64;
            #pragma unroll
            for (int ks = 0; ks < 2; ++ks) {
                uint32_t aF[2][4], bF[4][4];
                #pragma unroll
                for (int m = 0; m < 2; ++m)
                    ldsm4(aF[m], abase + m * (16 * A_STRIDE) + ks * 32);
                #pragma unroll
                for (int p = 0; p < 4; ++p)
                    ldsm4(bF[p], offB + bbuf + p * (16 * 80) + ks * 32);
                #pragma unroll
                for (int m = 0; m < 2; ++m)
                    #pragma unroll
                    for (int p = 0; p < 4; ++p) {
                        imma16832(acc[m][p * 2],     aF[m], &bF[p][0]);
                        imma16832(acc[m][p * 2 + 1], aF[m], &bF[p][2]);
                    }
            }
        }

        // integer-domain fold: s_i = en_i - acc ; rare-entry top-3 chain
        #pragma unroll
        for (int m = 0; m < 2; ++m)
            #pragma unroll
            for (int h = 0; h < 2; ++h) {
                const int slot = m * 2 + h;
                int v1 = vp[(0 * 4 + slot) * 256 + tid];
                int v2 = vp[(1 * 4 + slot) * 256 + tid];
                int v3 = vp[(2 * 4 + slot) * 256 + tid];
                uint32_t p12 = ip12[slot * 256 + tid];
                uint32_t p3  = ip3[slot * 256 + tid];
                int i1 = p12 >> 16, i2 = p12 & 0xffff, i3 = (int)p3;
                #pragma unroll
                for (int f = 0; f < 8; ++f) {
                    const int colb = t * 128 + wc * 64 + (f >> 1) * 16 + (f & 1) * 8
                                     + 2 * (lane & 3);
                    #pragma unroll
                    for (int q = 0; q < 2; ++q) {
                        const int col = colb + q;
                        const int s = __ldg(&g_enorm2i[col]) - acc[m][f][h * 2 + q];
                        if (s < v3) {
                            if (s < v1)      { v3 = v2; i3 = i2; v2 = v1; i2 = i1; v1 = s; i1 = col; }
                            else if (s < v2) { v3 = v2; i3 = i2; v2 = s; i2 = col; }
                            else             { v3 = s; i3 = col; }
                        }
                    }
                }
                vp[(0 * 4 + slot) * 256 + tid] = v1;
                vp[(1 * 4 + slot) * 256 + tid] = v2;
                vp[(2 * 4 + slot) * 256 + tid] = v3;
                ip12[slot * 256 + tid] = (uint32_t)(i1 << 16) | (uint32_t)i2;
                ip3[slot * 256 + tid]  = (uint32_t)i3;
            }
    }

    // dump candidates: key = (f16(s_i/128) << 16) | col ; [row][24]
    __syncthreads();
    uint32_t* keys = (uint32_t*)smem;            // reuse A region, 12 KB
    #pragma unroll
    for (int m = 0; m < 2; ++m)
        #pragma unroll
        for (int h = 0; h < 2; ++h) {
            const int slot = m * 2 + h;
            float v1 = (float)vp[(0 * 4 + slot) * 256 + tid] * 0.0078125f;
            float v2 = (float)vp[(1 * 4 + slot) * 256 + tid] * 0.0078125f;
            float v3 = (float)vp[(2 * 4 + slot) * 256 + tid] * 0.0078125f;
            uint32_t p12 = ip12[slot * 256 + tid];
            uint32_t p3  = ip3[slot * 256 + tid];
            int row = wr * 32 + m * 16 + h * 8 + (lane >> 2);
            int ent = (wc * 4 + (lane & 3)) * 3;
            keys[row * 24 + ent + 0] =
                ((uint32_t)__half_as_ushort(__float2half_rn(v1)) << 16) | (p12 >> 16);
            keys[row * 24 + ent + 1] =
                ((uint32_t)__half_as_ushort(__float2half_rn(v2)) << 16) | (p12 & 0xffff);
            keys[row * 24 + ent + 2] =
                ((uint32_t)__half_as_ushort(__float2half_rn(v3)) << 16) | (p3 & 0xffff);
        }
    __syncthreads();
    #pragma unroll
    for (int j = 0; j < 12; ++j) {
        int lin = tid + j * 256;                 // 0..3071
        g_cand[(size_t)mt * (128 * NCAND) + lin] = keys[lin];
    }
}

// ============================================================
// K3b: fused gated exact re-rank + gather, 2 rows per 256-thr block
// ============================================================
__global__ __launch_bounds__(256) void k_rerank(const float* __restrict__ X,
                                                const float* __restrict__ E,
                                                float* __restrict__ out) {
    __shared__ float xs[2][DIM];
    __shared__ unsigned int keys[2][32];
    __shared__ unsigned int mkey[2];
    __shared__ unsigned long long res[2];
    __shared__ float wsum[2][4];
    const int tid  = threadIdx.x;
    const int half = tid >> 7;                    // 0 or 1
    const int htid = tid & 127;
    const int row  = blockIdx.x * 2 + half;
    const int lane = tid & 31;
    const int warp = htid >> 5;                   // 0..3 within half

    if (htid < 32)
        keys[half][htid] = (htid < NCAND) ? g_cand[(size_t)row * NCAND + htid] : 0xFFFFFFFFu;
    *(float4*)(&xs[half][htid * 4]) = *(const float4*)(X + (size_t)row * DIM + htid * 4);
    if (htid == 0) res[half] = ~0ull;
    __syncthreads();

    if (htid < 32) {
        unsigned int m = __reduce_min_sync(0xffffffffu, keys[half][lane]);
        if (lane == 0) mkey[half] = m;
    }
    __syncthreads();

    const float thresh = __half2float(__ushort_as_half((unsigned short)(mkey[half] >> 16)))
                         + RERANK_THRESH;

    for (int c = warp; c < NCAND; c += 4) {
        unsigned int k = keys[half][c];
        float v = __half2float(__ushort_as_half((unsigned short)(k >> 16)));
        if (v <= thresh) {
            int col = (int)(k & 0xffffu);
            const float* er = E + (size_t)col * DIM;
            float dot = 0.0f;
            #pragma unroll
            for (int j = 0; j < 4; ++j) {
                float4 e = *(const float4*)(er + j * 128 + lane * 4);
                float4 x = *(const float4*)(&xs[half][j * 128 + lane * 4]);
                dot = fmaf(x.x, e.x, dot); dot = fmaf(x.y, e.y, dot);
                dot = fmaf(x.z, e.z, dot); dot = fmaf(x.w, e.w, dot);
            }
            #pragma unroll
            for (int o = 16; o; o >>= 1) dot += __shfl_xor_sync(0xffffffffu, dot, o);
            if (lane == 0) {
                float s = fmaf(-2.0f, dot, __ldg(&g_enorm2[col]));
                unsigned long long key64 =
                    ((unsigned long long)__float_as_uint(s) << 32) | (unsigned int)col;
                atomicMin(&res[half], key64);
            }
        }
    }
    __syncthreads();
    const int best = (int)(res[half] & 0xffffffffull);

    const float* er = E + (size_t)best * DIM;
    float* dwr = g_dw + (size_t)best * DIM;
    int d = htid * 4;
    float4 q = *(const float4*)(er + d);
    float4 x = *(const float4*)(&xs[half][d]);
    *(float4*)(out + O_Q + (size_t)row * DIM + d) = q;
    atomicAdd(dwr + d + 0, x.x);
    atomicAdd(dwr + d + 1, x.y);
    atomicAdd(dwr + d + 2, x.z);
    atomicAdd(dwr + d + 3, x.w);

    float dx = q.x - x.x, dy = q.y - x.y, dz = q.z - x.z, dw = q.w - x.w;
    float ls = dx * dx + dy * dy + dz * dz + dw * dw;
    #pragma unroll
    for (int o = 16; o; o >>= 1) ls += __shfl_xor_sync(0xffffffffu, ls, o);
    if (lane == 0) wsum[half][warp] = ls;
    __syncthreads();
    if (htid == 0) {
        atomicAdd(&g_loss_sum, wsum[half][0] + wsum[half][1] + wsum[half][2] + wsum[half][3]);
        atomicAdd(&g_counts[best], 1.0f);
    }
}

// ============================================================
// K5a/K5b/K6: EMA stats + finalize (unchanged, verified)
// ============================================================
__global__ __launch_bounds__(256) void k_stats1(const float* __restrict__ cs_in) {
    __shared__ float sn[8], sp[8];
    int k = blockIdx.x * 256 + threadIdx.x;
    float cnt = g_counts[k];
    float pre = fmaf(cs_in[k], DECAYF, OMDF * cnt);
    g_cs_pre[k] = pre;
    float p = cnt * (1.0f / (float)NROWS);
    float pl = p * logf(p + 1e-10f);
    float ns = pre, ps = pl;
    #pragma unroll
    for (int o = 16; o; o >>= 1) {
        ns += __shfl_xor_sync(0xffffffffu, ns, o);
        ps += __shfl_xor_sync(0xffffffffu, ps, o);
    }
    int lane = threadIdx.x & 31, warp = threadIdx.x >> 5;
    if (lane == 0) { sn[warp] = ns; sp[warp] = ps; }
    __syncthreads();
    if (threadIdx.x == 0) {
        float a = 0.0f, b = 0.0f;
        #pragma unroll
        for (int w = 0; w < 8; ++w) { a += sn[w]; b += sp[w]; }
        atomicAdd(&g_n_sum, a);
        atomicAdd(&g_plogp_sum, b);
    }
}

__global__ __launch_bounds__(256) void k_stats2(float* __restrict__ out) {
    int k = blockIdx.x * 256 + threadIdx.x;
    float n = g_n_sum;
    float ncs = (g_cs_pre[k] + EPSF) / (n + (float)KC * EPSF) * n;
    out[O_CS + k] = ncs;
    if (blockIdx.x == 0 && threadIdx.x == 0) {
        out[O_LOSS] = 0.25f * (g_loss_sum / (float)(NROWS * DIM));
        out[O_PERP] = expf(-g_plogp_sum);
    }
}

__global__ __launch_bounds__(256) void k_final(const float* __restrict__ ema_w,
                                               float* __restrict__ out) {
    const float* ncs = out + O_CS;
    int i = blockIdx.x * blockDim.x + threadIdx.x;
    int total = KC * DIM / 4;
    int stride = gridDim.x * blockDim.x;
    for (; i < total; i += stride) {
        int e = i * 4;
        int k = e >> 9;
        float4 w  = *(const float4*)(ema_w + e);
        float4 dv = *(const float4*)(g_dw + e);
        float4 nw;
        nw.x = fmaf(w.x, DECAYF, OMDF * dv.x);
        nw.y = fmaf(w.y, DECAYF, OMDF * dv.y);
        nw.z = fmaf(w.z, DECAYF, OMDF * dv.z);
        nw.w = fmaf(w.w, DECAYF, OMDF * dv.w);
        *(float2*)(out + O_W + e)     = make_float2(nw.x, nw.y);
        *(float2*)(out + O_W + e + 2) = make_float2(nw.z, nw.w);
        float inv = 1.0f / ncs[k];
        *(float2*)(out + O_EMB + e)     = make_float2(nw.x * inv, nw.y * inv);
        *(float2*)(out + O_EMB + e + 2) = make_float2(nw.z * inv, nw.w * inv);
    }
}

// ============================================================
extern "C" void kernel_launch(void* const* d_in, const int* in_sizes, int n_in,
                              void* d_out, int out_size) {
    const float* X     = (const float*)d_in[0];
    const float* E     = (const float*)d_in[1];
    const float* cs    = (const float*)d_in[2];
    const float* ema_w = (const float*)d_in[3];
    float* out = (float*)d_out;

    cudaFuncSetAttribute(k_argmin_mma, cudaFuncAttributeMaxDynamicSharedMemorySize, SMEM_MMA);

    k_prep  <<<4096, 256>>>(X, E);
    k_enorm2<<<KC / 8, 256>>>(E);
    k_argmin_mma<<<NROWS / 128, 256, SMEM_MMA>>>();
    k_rerank<<<NROWS / 2, 256>>>(X, E, out);
    k_stats1<<<KC / 256, 256>>>(cs);
    k_stats2<<<KC / 256, 256>>>(out);
    k_final <<<2048, 256>>>(ema_w, out);
}

// round 11
// speedup vs baseline: 11.4473x; 1.0159x over previous
#include <cuda_runtime.h>
#include <cuda_fp16.h>
#include <math.h>
#include <float.h>
#include <stdint.h>
#include <limits.h>

// Problem constants
#define NROWS 32768
#define KC    8192
#define DIM   512

#define DECAYF 0.99f
#define OMDF   0.01f
#define EPSF   1e-5f

#define NCAND 24              // 8 owner threads x top-3 per row
#define RERANK_THRESH 10.0f   // int8 distance err sigma ~1.2 -> 8.6 sigma gate
#define QSCALE 16.0f          // acc = 256*(x.e)_q ; s*128 = en*128 - acc

// ============================================================
// scratch (device globals)
// ============================================================
__device__ float g_enorm2[KC];
__device__ int   g_enorm2i[KC];       // round(128 * ||e||^2)
__device__ unsigned int g_cand[NROWS * NCAND];
__device__ float g_counts[KC];
__device__ float g_dw[KC * DIM];
__device__ float g_cs_pre[KC];
__device__ float g_loss_sum;
__device__ float g_n_sum;
__device__ float g_plogp_sum;

// int8 operands, row-major [rows][512]
__device__ int8_t g_xs8[NROWS * DIM];
__device__ int8_t g_es8[KC * DIM];

// ---- output layout (O_EMB/O_W only 8-byte aligned -> float2 there) ----
#define O_Q    0
#define O_LOSS (NROWS * DIM)
#define O_PERP (O_LOSS + 1)
#define O_EMB  (O_PERP + 1)
#define O_CS   (O_EMB + KC * DIM)
#define O_W    (O_CS + KC)

// ============================================================
// PTX helpers (baseline compute_100 = sm_80+/sm_90+ features only)
// ============================================================
__device__ __forceinline__ uint32_t smem_u32(const void* p) {
    uint32_t a;
    asm("{ .reg .u64 t; cvta.to.shared.u64 t, %1; cvt.u32.u64 %0, t; }" : "=r"(a) : "l"(p));
    return a;
}
__device__ __forceinline__ void cp16(uint32_t dst, const void* src) {
    asm volatile("cp.async.cg.shared.global [%0], [%1], 16;" :: "r"(dst), "l"(src) : "memory");
}
__device__ __forceinline__ void cp_commit() { asm volatile("cp.async.commit_group;" ::: "memory"); }
__device__ __forceinline__ void cp_wait0()  { asm volatile("cp.async.wait_group 0;" ::: "memory"); }

__device__ __forceinline__ void ldsm4(uint32_t* r, uint32_t addr) {
    asm volatile("ldmatrix.sync.aligned.m8n8.x4.shared.b16 {%0,%1,%2,%3}, [%4];"
        : "=r"(r[0]), "=r"(r[1]), "=r"(r[2]), "=r"(r[3]) : "r"(addr));
}
__device__ __forceinline__ void imma16832(int* c, const uint32_t* a, const uint32_t* b) {
    asm volatile(
        "mma.sync.aligned.m16n8k32.row.col.s32.s8.s8.s32 "
        "{%0,%1,%2,%3}, {%4,%5,%6,%7}, {%8,%9}, {%0,%1,%2,%3};"
        : "+r"(c[0]), "+r"(c[1]), "+r"(c[2]), "+r"(c[3])
        : "r"(a[0]), "r"(a[1]), "r"(a[2]), "r"(a[3]), "r"(b[0]), "r"(b[1]));
}

// ============================================================
// K0: fused prep — convert X/E to int8, zero accumulators
// ============================================================
__device__ __forceinline__ uint32_t quant4(float4 v) {
    int q0 = max(-127, min(127, __float2int_rn(v.x * QSCALE)));
    int q1 = max(-127, min(127, __float2int_rn(v.y * QSCALE)));
    int q2 = max(-127, min(127, __float2int_rn(v.z * QSCALE)));
    int q3 = max(-127, min(127, __float2int_rn(v.w * QSCALE)));
    return (uint32_t)(q0 & 0xff) | ((uint32_t)(q1 & 0xff) << 8)
         | ((uint32_t)(q2 & 0xff) << 16) | ((uint32_t)(q3 & 0xff) << 24);
}

__global__ __launch_bounds__(256) void k_prep(const float* __restrict__ X,
                                              const float* __restrict__ E) {
    const int gid = blockIdx.x * blockDim.x + threadIdx.x;
    const int stride = gridDim.x * blockDim.x;
    const int n4x = NROWS * DIM / 4;
    const int n4e = KC * DIM / 4;
    for (int g = gid; g < n4x; g += stride)
        ((uint32_t*)g_xs8)[g] = quant4(*(const float4*)(X + (size_t)g * 4));
    for (int g = gid; g < n4e; g += stride)
        ((uint32_t*)g_es8)[g] = quant4(*(const float4*)(E + (size_t)g * 4));
    for (int i = gid; i < KC * DIM / 4; i += stride)
        *(float4*)(g_dw + (size_t)i * 4) = make_float4(0.f, 0.f, 0.f, 0.f);
    if (gid < KC) g_counts[gid] = 0.0f;
    if (gid == 0) { g_loss_sum = 0.0f; g_n_sum = 0.0f; g_plogp_sum = 0.0f; }
}

// ============================================================
// K2: ||e_k||^2 (fp32 + int*128 variants, one warp per code row)
// ============================================================
__global__ __launch_bounds__(256) void k_enorm2(const float* __restrict__ E) {
    int warp = (blockIdx.x * blockDim.x + threadIdx.x) >> 5;
    int lane = threadIdx.x & 31;
    if (warp >= KC) return;
    const float* row = E + (size_t)warp * DIM;
    float s = 0.0f;
    #pragma unroll
    for (int d = lane * 4; d < DIM; d += 32 * 4) {
        float4 v = *(const float4*)(row + d);
        s = fmaf(v.x, v.x, s); s = fmaf(v.y, v.y, s);
        s = fmaf(v.z, v.z, s); s = fmaf(v.w, v.w, s);
    }
    #pragma unroll
    for (int o = 16; o; o >>= 1) s += __shfl_xor_sync(0xffffffffu, s, o);
    if (lane == 0) {
        g_enorm2[warp] = s;
        g_enorm2i[warp] = __float2int_rn(s * 128.0f);
    }
}

// ============================================================
// K3: int8 IMMA GEMM, A resident, INTEGER-domain top-3 fold.
// ============================================================
#define SM_A     0
#define A_STRIDE 528
#define A_BYTES  (128 * A_STRIDE)          // 67584
#define SM_B     A_BYTES
#define TILE_BB  10240                     // 128 * 80
#define TOPV     (SM_B + 2 * TILE_BB)      // int planes [3][4][256] = 12 KB
#define TOPI12   (TOPV + 12288)
#define TOPI3    (TOPI12 + 4096)
#define SMEM_MMA (TOPI3 + 4096)            // 108544

__global__ __launch_bounds__(256, 2) void k_argmin_mma() {
    extern __shared__ char smem[];
    const uint32_t sb = smem_u32(smem);
    const int tid = threadIdx.x;
    const int lane = tid & 31;
    const int wid = tid >> 5;
    const int wr = wid >> 1;            // 0..3 : 32-row band
    const int wc = wid & 1;             // 0..1 : 64-col band
    const int mt = blockIdx.x;

    // ---- stage A resident ----
    {
        const int8_t* Ab = g_xs8 + (size_t)mt * 128 * DIM;
        #pragma unroll
        for (int i = 0; i < 16; ++i) {
            int seg = tid + i * 256;
            int r = seg >> 5, cs = seg & 31;
            cp16(sb + SM_A + r * A_STRIDE + cs * 16, Ab + (size_t)r * DIM + cs * 16);
        }
        cp_commit();
    }

    const uint32_t offA = sb + (uint32_t)(SM_A + (wr * 32 + (lane & 15)) * A_STRIDE
                                          + (lane >> 4) * 16);
    const uint32_t offB = sb + (uint32_t)(SM_B + (wc * 64 + (lane & 7) + ((lane >> 4) & 1) * 8) * 80
                                          + ((lane >> 3) & 1) * 16);

    int* vp = (int*)(smem + TOPV);
    uint32_t* ip12 = (uint32_t*)(smem + TOPI12);
    uint32_t* ip3  = (uint32_t*)(smem + TOPI3);
    #pragma unroll
    for (int j = 0; j < 3; ++j)
        #pragma unroll
        for (int s = 0; s < 4; ++s) vp[(j * 4 + s) * 256 + tid] = INT_MAX;
    #pragma unroll
    for (int s = 0; s < 4; ++s) { ip12[s * 256 + tid] = 0; ip3[s * 256 + tid] = 0; }

    // stage B chunk 0 of tile 0
    {
        const int8_t* Bb = g_es8;
        #pragma unroll
        for (int i = 0; i < 2; ++i) {
            int seg = tid + i * 256;
            int r = seg >> 2, cs = seg & 3;
            cp16(sb + SM_B + r * 80 + cs * 16, Bb + (size_t)r * DIM + cs * 16);
        }
        cp_commit();
    }

    #pragma unroll 1
    for (int t = 0; t < KC / 128; ++t) {
        const int8_t* Bb = g_es8 + (size_t)t * 128 * DIM;
        int acc[2][8][4];
        #pragma unroll
        for (int m = 0; m < 2; ++m)
            #pragma unroll
            for (int n = 0; n < 8; ++n)
                #pragma unroll
                for (int r = 0; r < 4; ++r) acc[m][n][r] = 0;

        #pragma unroll 1
        for (int c = 0; c < 8; ++c) {
            cp_wait0();
            __syncthreads();
            if (c + 1 < 8 || t + 1 < KC / 128) {
                const int8_t* Bn = (c + 1 < 8) ? Bb : (g_es8 + (size_t)(t + 1) * 128 * DIM);
                const int cn = (c + 1) & 7;
                const uint32_t bdst = sb + SM_B + ((c + 1) & 1) * TILE_BB;
                #pragma unroll
                for (int i = 0; i < 2; ++i) {
                    int seg = tid + i * 256;
                    int r = seg >> 2, cs = seg & 3;
                    cp16(bdst + r * 80 + cs * 16, Bn + (size_t)r * DIM + cn * 64 + cs * 16);
                }
                cp_commit();
            }
            const uint32_t bbuf = (uint32_t)((c & 1) * TILE_BB);
            const uint32_t abase = offA + c * 64;
            #pragma unroll
            for (int ks = 0; ks < 2; ++ks) {
                uint32_t aF[2][4], bF[4][4];
                #pragma unroll
                for (int m = 0; m < 2; ++m)
                    ldsm4(aF[m], abase + m * (16 * A_STRIDE) + ks * 32);
                #pragma unroll
                for (int p = 0; p < 4; ++p)
                    ldsm4(bF[p], offB + bbuf + p * (16 * 80) + ks * 32);
                #pragma unroll
                for (int m = 0; m < 2; ++m)
                    #pragma unroll
                    for (int p = 0; p < 4; ++p) {
                        imma16832(acc[m][p * 2],     aF[m], &bF[p][0]);
                        imma16832(acc[m][p * 2 + 1], aF[m], &bF[p][2]);
                    }
            }
        }

        // integer-domain fold: s_i = en_i - acc ; rare-entry top-3 chain
        #pragma unroll
        for (int m = 0; m < 2; ++m)
            #pragma unroll
            for (int h = 0; h < 2; ++h) {
                const int slot = m * 2 + h;
                int v1 = vp[(0 * 4 + slot) * 256 + tid];
                int v2 = vp[(1 * 4 + slot) * 256 + tid];
                int v3 = vp[(2 * 4 + slot) * 256 + tid];
                uint32_t p12 = ip12[slot * 256 + tid];
                uint32_t p3  = ip3[slot * 256 + tid];
                int i1 = p12 >> 16, i2 = p12 & 0xffff, i3 = (int)p3;
                #pragma unroll
                for (int f = 0; f < 8; ++f) {
                    const int colb = t * 128 + wc * 64 + (f >> 1) * 16 + (f & 1) * 8
                                     + 2 * (lane & 3);
                    #pragma unroll
                    for (int q = 0; q < 2; ++q) {
                        const int col = colb + q;
                        const int s = __ldg(&g_enorm2i[col]) - acc[m][f][h * 2 + q];
                        if (s < v3) {
                            if (s < v1)      { v3 = v2; i3 = i2; v2 = v1; i2 = i1; v1 = s; i1 = col; }
                            else if (s < v2) { v3 = v2; i3 = i2; v2 = s; i2 = col; }
                            else             { v3 = s; i3 = col; }
                        }
                    }
                }
                vp[(0 * 4 + slot) * 256 + tid] = v1;
                vp[(1 * 4 + slot) * 256 + tid] = v2;
                vp[(2 * 4 + slot) * 256 + tid] = v3;
                ip12[slot * 256 + tid] = (uint32_t)(i1 << 16) | (uint32_t)i2;
                ip3[slot * 256 + tid]  = (uint32_t)i3;
            }
    }

    // dump candidates: key = (f16(s_i/128) << 16) | col ; [row][24]
    __syncthreads();
    uint32_t* keys = (uint32_t*)smem;            // reuse A region, 12 KB
    #pragma unroll
    for (int m = 0; m < 2; ++m)
        #pragma unroll
        for (int h = 0; h < 2; ++h) {
            const int slot = m * 2 + h;
            float v1 = (float)vp[(0 * 4 + slot) * 256 + tid] * 0.0078125f;
            float v2 = (float)vp[(1 * 4 + slot) * 256 + tid] * 0.0078125f;
            float v3 = (float)vp[(2 * 4 + slot) * 256 + tid] * 0.0078125f;
            uint32_t p12 = ip12[slot * 256 + tid];
            uint32_t p3  = ip3[slot * 256 + tid];
            int row = wr * 32 + m * 16 + h * 8 + (lane >> 2);
            int ent = (wc * 4 + (lane & 3)) * 3;
            keys[row * 24 + ent + 0] =
                ((uint32_t)__half_as_ushort(__float2half_rn(v1)) << 16) | (p12 >> 16);
            keys[row * 24 + ent + 1] =
                ((uint32_t)__half_as_ushort(__float2half_rn(v2)) << 16) | (p12 & 0xffff);
            keys[row * 24 + ent + 2] =
                ((uint32_t)__half_as_ushort(__float2half_rn(v3)) << 16) | (p3 & 0xffff);
        }
    __syncthreads();
    #pragma unroll
    for (int j = 0; j < 12; ++j) {
        int lin = tid + j * 256;                 // 0..3071
        g_cand[(size_t)mt * (128 * NCAND) + lin] = keys[lin];
    }
}

// ============================================================
// K3b: fused gated exact re-rank + gather, 2 rows per 256-thr block
// dw scatter uses float4 vector atomics (sm_90+) — 4x fewer RED ops.
// ============================================================
__global__ __launch_bounds__(256) void k_rerank(const float* __restrict__ X,
                                                const float* __restrict__ E,
                                                float* __restrict__ out) {
    __shared__ float xs[2][DIM];
    __shared__ unsigned int keys[2][32];
    __shared__ unsigned int mkey[2];
    __shared__ unsigned long long res[2];
    __shared__ float wsum[2][4];
    const int tid  = threadIdx.x;
    const int half = tid >> 7;                    // 0 or 1
    const int htid = tid & 127;
    const int row  = blockIdx.x * 2 + half;
    const int lane = tid & 31;
    const int warp = htid >> 5;                   // 0..3 within half

    if (htid < 32)
        keys[half][htid] = (htid < NCAND) ? g_cand[(size_t)row * NCAND + htid] : 0xFFFFFFFFu;
    *(float4*)(&xs[half][htid * 4]) = *(const float4*)(X + (size_t)row * DIM + htid * 4);
    if (htid == 0) res[half] = ~0ull;
    __syncthreads();

    if (htid < 32) {
        unsigned int m = __reduce_min_sync(0xffffffffu, keys[half][lane]);
        if (lane == 0) mkey[half] = m;
    }
    __syncthreads();

    const float thresh = __half2float(__ushort_as_half((unsigned short)(mkey[half] >> 16)))
                         + RERANK_THRESH;

    for (int c = warp; c < NCAND; c += 4) {
        unsigned int k = keys[half][c];
        float v = __half2float(__ushort_as_half((unsigned short)(k >> 16)));
        if (v <= thresh) {
            int col = (int)(k & 0xffffu);
            const float* er = E + (size_t)col * DIM;
            float dot = 0.0f;
            #pragma unroll
            for (int j = 0; j < 4; ++j) {
                float4 e = *(const float4*)(er + j * 128 + lane * 4);
                float4 x = *(const float4*)(&xs[half][j * 128 + lane * 4]);
                dot = fmaf(x.x, e.x, dot); dot = fmaf(x.y, e.y, dot);
                dot = fmaf(x.z, e.z, dot); dot = fmaf(x.w, e.w, dot);
            }
            #pragma unroll
            for (int o = 16; o; o >>= 1) dot += __shfl_xor_sync(0xffffffffu, dot, o);
            if (lane == 0) {
                float s = fmaf(-2.0f, dot, __ldg(&g_enorm2[col]));
                unsigned long long key64 =
                    ((unsigned long long)__float_as_uint(s) << 32) | (unsigned int)col;
                atomicMin(&res[half], key64);
            }
        }
    }
    __syncthreads();
    const int best = (int)(res[half] & 0xffffffffull);

    const float* er = E + (size_t)best * DIM;
    float* dwr = g_dw + (size_t)best * DIM;
    int d = htid * 4;
    float4 q = *(const float4*)(er + d);
    float4 x = *(const float4*)(&xs[half][d]);
    *(float4*)(out + O_Q + (size_t)row * DIM + d) = q;
    atomicAdd((float4*)(dwr + d), x);            // vector RED.128 (sm_90+)

    float dx = q.x - x.x, dy = q.y - x.y, dz = q.z - x.z, dw = q.w - x.w;
    float ls = dx * dx + dy * dy + dz * dz + dw * dw;
    #pragma unroll
    for (int o = 16; o; o >>= 1) ls += __shfl_xor_sync(0xffffffffu, ls, o);
    if (lane == 0) wsum[half][warp] = ls;
    __syncthreads();
    if (htid == 0) {
        atomicAdd(&g_loss_sum, wsum[half][0] + wsum[half][1] + wsum[half][2] + wsum[half][3]);
        atomicAdd(&g_counts[best], 1.0f);
    }
}

// ============================================================
// K5a: EMA cluster-size pre + global sums
// ============================================================
__global__ __launch_bounds__(256) void k_stats1(const float* __restrict__ cs_in) {
    __shared__ float sn[8], sp[8];
    int k = blockIdx.x * 256 + threadIdx.x;
    float cnt = g_counts[k];
    float pre = fmaf(cs_in[k], DECAYF, OMDF * cnt);
    g_cs_pre[k] = pre;
    float p = cnt * (1.0f / (float)NROWS);
    float pl = p * logf(p + 1e-10f);
    float ns = pre, ps = pl;
    #pragma unroll
    for (int o = 16; o; o >>= 1) {
        ns += __shfl_xor_sync(0xffffffffu, ns, o);
        ps += __shfl_xor_sync(0xffffffffu, ps, o);
    }
    int lane = threadIdx.x & 31, warp = threadIdx.x >> 5;
    if (lane == 0) { sn[warp] = ns; sp[warp] = ps; }
    __syncthreads();
    if (threadIdx.x == 0) {
        float a = 0.0f, b = 0.0f;
        #pragma unroll
        for (int w = 0; w < 8; ++w) { a += sn[w]; b += sp[w]; }
        atomicAdd(&g_n_sum, a);
        atomicAdd(&g_plogp_sum, b);
    }
}

// ============================================================
// K6: finalize (merged stats2): new_cs, loss, perplexity,
//     new_w = ema_w*decay + (1-decay)*dw, new_emb = new_w / new_cs.
// ============================================================
__global__ __launch_bounds__(256) void k_final(const float* __restrict__ ema_w,
                                               float* __restrict__ out) {
    const float n = g_n_sum;
    const float inv_den = 1.0f / (n + (float)KC * EPSF);
    if (blockIdx.x == 0 && threadIdx.x == 0) {
        out[O_LOSS] = 0.25f * (g_loss_sum / (float)(NROWS * DIM));
        out[O_PERP] = expf(-g_plogp_sum);
    }
    int i = blockIdx.x * blockDim.x + threadIdx.x;
    int total = KC * DIM / 4;
    int stride = gridDim.x * blockDim.x;
    for (; i < total; i += stride) {
        int e = i * 4;
        int k = e >> 9;
        float ncs = (g_cs_pre[k] + EPSF) * inv_den * n;
        if ((e & (DIM - 1)) == 0) out[O_CS + k] = ncs;
        float4 w  = *(const float4*)(ema_w + e);
        float4 dv = *(const float4*)(g_dw + e);
        float4 nw;
        nw.x = fmaf(w.x, DECAYF, OMDF * dv.x);
        nw.y = fmaf(w.y, DECAYF, OMDF * dv.y);
        nw.z = fmaf(w.z, DECAYF, OMDF * dv.z);
        nw.w = fmaf(w.w, DECAYF, OMDF * dv.w);
        *(float2*)(out + O_W + e)     = make_float2(nw.x, nw.y);
        *(float2*)(out + O_W + e + 2) = make_float2(nw.z, nw.w);
        float inv = 1.0f / ncs;
        *(float2*)(out + O_EMB + e)     = make_float2(nw.x * inv, nw.y * inv);
        *(float2*)(out + O_EMB + e + 2) = make_float2(nw.z * inv, nw.w * inv);
    }
}

// ============================================================
extern "C" void kernel_launch(void* const* d_in, const int* in_sizes, int n_in,
                              void* d_out, int out_size) {
    const float* X     = (const float*)d_in[0];
    const float* E     = (const float*)d_in[1];
    const float* cs    = (const float*)d_in[2];
    const float* ema_w = (const float*)d_in[3];
    float* out = (float*)d_out;

    cudaFuncSetAttribute(k_argmin_mma, cudaFuncAttributeMaxDynamicSharedMemorySize, SMEM_MMA);

    k_prep  <<<4096, 256>>>(X, E);
    k_enorm2<<<KC / 8, 256>>>(E);
    k_argmin_mma<<<NROWS / 128, 256, SMEM_MMA>>>();
    k_rerank<<<NROWS / 2, 256>>>(X, E, out);
    k_stats1<<<KC / 256, 256>>>(cs);
    k_final <<<2048, 256>>>(ema_w, out);
}

// round 12
// speedup vs baseline: 12.1032x; 1.0573x over previous
#include <cuda_runtime.h>
#include <cuda_fp16.h>
#include <math.h>
#include <float.h>
#include <stdint.h>
#include <limits.h>

// Problem constants
#define NROWS 32768
#define KC    8192
#define DIM   512

#define DECAYF 0.99f
#define OMDF   0.01f
#define EPSF   1e-5f

#define NCAND 24              // 8 owner threads x top-3 per row
#define RERANK_THRESH 10.0f   // int8 distance err sigma ~1.2 -> 8.6 sigma gate
#define QSCALE 16.0f          // acc = 256*(x.e)_q ; s*128 = en*128 - acc

// ============================================================
// scratch (device globals)
// ============================================================
__device__ float g_enorm2[KC];
__device__ int   g_enorm2i[KC];       // round(128 * ||e||^2)
__device__ unsigned int g_cand[NROWS * NCAND];
__device__ float g_counts[KC];
__device__ float g_dw[KC * DIM];
__device__ float g_cs_pre[KC];
__device__ float g_loss_sum;
__device__ float g_n_sum;
__device__ float g_plogp_sum;

// int8 operands, row-major [rows][512]
__device__ int8_t g_xs8[NROWS * DIM];
__device__ int8_t g_es8[KC * DIM];

// ---- output layout (O_EMB/O_W only 8-byte aligned -> float2 there) ----
#define O_Q    0
#define O_LOSS (NROWS * DIM)
#define O_PERP (O_LOSS + 1)
#define O_EMB  (O_PERP + 1)
#define O_CS   (O_EMB + KC * DIM)
#define O_W    (O_CS + KC)

// ============================================================
// PTX helpers (baseline compute_100 = sm_80+/sm_90+ features only)
// ============================================================
__device__ __forceinline__ uint32_t smem_u32(const void* p) {
    uint32_t a;
    asm("{ .reg .u64 t; cvta.to.shared.u64 t, %1; cvt.u32.u64 %0, t; }" : "=r"(a) : "l"(p));
    return a;
}
__device__ __forceinline__ void cp16(uint32_t dst, const void* src) {
    asm volatile("cp.async.cg.shared.global [%0], [%1], 16;" :: "r"(dst), "l"(src) : "memory");
}
__device__ __forceinline__ void cp_commit() { asm volatile("cp.async.commit_group;" ::: "memory"); }
__device__ __forceinline__ void cp_wait0()  { asm volatile("cp.async.wait_group 0;" ::: "memory"); }

__device__ __forceinline__ void ldsm4(uint32_t* r, uint32_t addr) {
    asm volatile("ldmatrix.sync.aligned.m8n8.x4.shared.b16 {%0,%1,%2,%3}, [%4];"
        : "=r"(r[0]), "=r"(r[1]), "=r"(r[2]), "=r"(r[3]) : "r"(addr));
}
__device__ __forceinline__ void imma16832(int* c, const uint32_t* a, const uint32_t* b) {
    asm volatile(
        "mma.sync.aligned.m16n8k32.row.col.s32.s8.s8.s32 "
        "{%0,%1,%2,%3}, {%4,%5,%6,%7}, {%8,%9}, {%0,%1,%2,%3};"
        : "+r"(c[0]), "+r"(c[1]), "+r"(c[2]), "+r"(c[3])
        : "r"(a[0]), "r"(a[1]), "r"(a[2]), "r"(a[3]), "r"(b[0]), "r"(b[1]));
}

// ============================================================
// K0: fused prep — int8 convert, zero accumulators, E norms
// ============================================================
__device__ __forceinline__ uint32_t quant4(float4 v) {
    int q0 = max(-127, min(127, __float2int_rn(v.x * QSCALE)));
    int q1 = max(-127, min(127, __float2int_rn(v.y * QSCALE)));
    int q2 = max(-127, min(127, __float2int_rn(v.z * QSCALE)));
    int q3 = max(-127, min(127, __float2int_rn(v.w * QSCALE)));
    return (uint32_t)(q0 & 0xff) | ((uint32_t)(q1 & 0xff) << 8)
         | ((uint32_t)(q2 & 0xff) << 16) | ((uint32_t)(q3 & 0xff) << 24);
}

__global__ __launch_bounds__(256) void k_prep(const float* __restrict__ X,
                                              const float* __restrict__ E) {
    const int gid = blockIdx.x * blockDim.x + threadIdx.x;
    const int stride = gridDim.x * blockDim.x;
    const int n4x = NROWS * DIM / 4;
    const int n4e = KC * DIM / 4;
    for (int g = gid; g < n4x; g += stride)
        ((uint32_t*)g_xs8)[g] = quant4(*(const float4*)(X + (size_t)g * 4));
    for (int g = gid; g < n4e; g += stride)
        ((uint32_t*)g_es8)[g] = quant4(*(const float4*)(E + (size_t)g * 4));
    for (int i = gid; i < KC * DIM / 4; i += stride)
        *(float4*)(g_dw + (size_t)i * 4) = make_float4(0.f, 0.f, 0.f, 0.f);
    if (gid < KC) g_counts[gid] = 0.0f;
    if (gid == 0) { g_loss_sum = 0.0f; g_n_sum = 0.0f; g_plogp_sum = 0.0f; }

    // E row norms: one warp per code row (independent of loops above)
    const int lane = threadIdx.x & 31;
    const int warp = gid >> 5;
    const int nwarps = stride >> 5;
    for (int k = warp; k < KC; k += nwarps) {
        const float* row = E + (size_t)k * DIM;
        float s = 0.0f;
        #pragma unroll
        for (int d = lane * 4; d < DIM; d += 128) {
            float4 v = *(const float4*)(row + d);
            s = fmaf(v.x, v.x, s); s = fmaf(v.y, v.y, s);
            s = fmaf(v.z, v.z, s); s = fmaf(v.w, v.w, s);
        }
        #pragma unroll
        for (int o = 16; o; o >>= 1) s += __shfl_xor_sync(0xffffffffu, s, o);
        if (lane == 0) {
            g_enorm2[k] = s;
            g_enorm2i[k] = __float2int_rn(s * 128.0f);
        }
    }
}

// ============================================================
// K3: int8 IMMA GEMM, A resident, INTEGER-domain top-3 fold.
// ============================================================
#define SM_A     0
#define A_STRIDE 528
#define A_BYTES  (128 * A_STRIDE)          // 67584
#define SM_B     A_BYTES
#define TILE_BB  10240                     // 128 * 80
#define TOPV     (SM_B + 2 * TILE_BB)      // int planes [3][4][256] = 12 KB
#define TOPI12   (TOPV + 12288)
#define TOPI3    (TOPI12 + 4096)
#define SMEM_MMA (TOPI3 + 4096)            // 108544

__global__ __launch_bounds__(256, 2) void k_argmin_mma() {
    extern __shared__ char smem[];
    const uint32_t sb = smem_u32(smem);
    const int tid = threadIdx.x;
    const int lane = tid & 31;
    const int wid = tid >> 5;
    const int wr = wid >> 1;            // 0..3 : 32-row band
    const int wc = wid & 1;             // 0..1 : 64-col band
    const int mt = blockIdx.x;

    // ---- stage A resident ----
    {
        const int8_t* Ab = g_xs8 + (size_t)mt * 128 * DIM;
        #pragma unroll
        for (int i = 0; i < 16; ++i) {
            int seg = tid + i * 256;
            int r = seg >> 5, cs = seg & 31;
            cp16(sb + SM_A + r * A_STRIDE + cs * 16, Ab + (size_t)r * DIM + cs * 16);
        }
        cp_commit();
    }

    const uint32_t offA = sb + (uint32_t)(SM_A + (wr * 32 + (lane & 15)) * A_STRIDE
                                          + (lane >> 4) * 16);
    const uint32_t offB = sb + (uint32_t)(SM_B + (wc * 64 + (lane & 7) + ((lane >> 4) & 1) * 8) * 80
                                          + ((lane >> 3) & 1) * 16);

    int* vp = (int*)(smem + TOPV);
    uint32_t* ip12 = (uint32_t*)(smem + TOPI12);
    uint32_t* ip3  = (uint32_t*)(smem + TOPI3);
    #pragma unroll
    for (int j = 0; j < 3; ++j)
        #pragma unroll
        for (int s = 0; s < 4; ++s) vp[(j * 4 + s) * 256 + tid] = INT_MAX;
    #pragma unroll
    for (int s = 0; s < 4; ++s) { ip12[s * 256 + tid] = 0; ip3[s * 256 + tid] = 0; }

    // stage B chunk 0 of tile 0
    {
        const int8_t* Bb = g_es8;
        #pragma unroll
        for (int i = 0; i < 2; ++i) {
            int seg = tid + i * 256;
            int r = seg >> 2, cs = seg & 3;
            cp16(sb + SM_B + r * 80 + cs * 16, Bb + (size_t)r * DIM + cs * 16);
        }
        cp_commit();
    }

    #pragma unroll 1
    for (int t = 0; t < KC / 128; ++t) {
        const int8_t* Bb = g_es8 + (size_t)t * 128 * DIM;
        int acc[2][8][4];
        #pragma unroll
        for (int m = 0; m < 2; ++m)
            #pragma unroll
            for (int n = 0; n < 8; ++n)
                #pragma unroll
                for (int r = 0; r < 4; ++r) acc[m][n][r] = 0;

        #pragma unroll 1
        for (int c = 0; c < 8; ++c) {
            cp_wait0();
            __syncthreads();
            if (c + 1 < 8 || t + 1 < KC / 128) {
                const int8_t* Bn = (c + 1 < 8) ? Bb : (g_es8 + (size_t)(t + 1) * 128 * DIM);
                const int cn = (c + 1) & 7;
                const uint32_t bdst = sb + SM_B + ((c + 1) & 1) * TILE_BB;
                #pragma unroll
                for (int i = 0; i < 2; ++i) {
                    int seg = tid + i * 256;
                    int r = seg >> 2, cs = seg & 3;
                    cp16(bdst + r * 80 + cs * 16, Bn + (size_t)r * DIM + cn * 64 + cs * 16);
                }
                cp_commit();
            }
            const uint32_t bbuf = (uint32_t)((c & 1) * TILE_BB);
            const uint32_t abase = offA + c * 64;
            #pragma unroll
            for (int ks = 0; ks < 2; ++ks) {
                uint32_t aF[2][4], bF[4][4];
                #pragma unroll
                for (int m = 0; m < 2; ++m)
                    ldsm4(aF[m], abase + m * (16 * A_STRIDE) + ks * 32);
                #pragma unroll
                for (int p = 0; p < 4; ++p)
                    ldsm4(bF[p], offB + bbuf + p * (16 * 80) + ks * 32);
                #pragma unroll
                for (int m = 0; m < 2; ++m)
                    #pragma unroll
                    for (int p = 0; p < 4; ++p) {
                        imma16832(acc[m][p * 2],     aF[m], &bF[p][0]);
                        imma16832(acc[m][p * 2 + 1], aF[m], &bF[p][2]);
                    }
            }
        }

        // integer-domain fold: s_i = en_i - acc ; rare-entry top-3 chain
        #pragma unroll
        for (int m = 0; m < 2; ++m)
            #pragma unroll
            for (int h = 0; h < 2; ++h) {
                const int slot = m * 2 + h;
                int v1 = vp[(0 * 4 + slot) * 256 + tid];
                int v2 = vp[(1 * 4 + slot) * 256 + tid];
                int v3 = vp[(2 * 4 + slot) * 256 + tid];
                uint32_t p12 = ip12[slot * 256 + tid];
                uint32_t p3  = ip3[slot * 256 + tid];
                int i1 = p12 >> 16, i2 = p12 & 0xffff, i3 = (int)p3;
                #pragma unroll
                for (int f = 0; f < 8; ++f) {
                    const int colb = t * 128 + wc * 64 + (f >> 1) * 16 + (f & 1) * 8
                                     + 2 * (lane & 3);
                    #pragma unroll
                    for (int q = 0; q < 2; ++q) {
                        const int col = colb + q;
                        const int s = __ldg(&g_enorm2i[col]) - acc[m][f][h * 2 + q];
                        if (s < v3) {
                            if (s < v1)      { v3 = v2; i3 = i2; v2 = v1; i2 = i1; v1 = s; i1 = col; }
                            else if (s < v2) { v3 = v2; i3 = i2; v2 = s; i2 = col; }
                            else             { v3 = s; i3 = col; }
                        }
                    }
                }
                vp[(0 * 4 + slot) * 256 + tid] = v1;
                vp[(1 * 4 + slot) * 256 + tid] = v2;
                vp[(2 * 4 + slot) * 256 + tid] = v3;
                ip12[slot * 256 + tid] = (uint32_t)(i1 << 16) | (uint32_t)i2;
                ip3[slot * 256 + tid]  = (uint32_t)i3;
            }
    }

    // dump candidates: key = (f16(s_i/128) << 16) | col ; [row][24]
    __syncthreads();
    uint32_t* keys = (uint32_t*)smem;            // reuse A region, 12 KB
    #pragma unroll
    for (int m = 0; m < 2; ++m)
        #pragma unroll
        for (int h = 0; h < 2; ++h) {
            const int slot = m * 2 + h;
            float v1 = (float)vp[(0 * 4 + slot) * 256 + tid] * 0.0078125f;
            float v2 = (float)vp[(1 * 4 + slot) * 256 + tid] * 0.0078125f;
            float v3 = (float)vp[(2 * 4 + slot) * 256 + tid] * 0.0078125f;
            uint32_t p12 = ip12[slot * 256 + tid];
            uint32_t p3  = ip3[slot * 256 + tid];
            int row = wr * 32 + m * 16 + h * 8 + (lane >> 2);
            int ent = (wc * 4 + (lane & 3)) * 3;
            keys[row * 24 + ent + 0] =
                ((uint32_t)__half_as_ushort(__float2half_rn(v1)) << 16) | (p12 >> 16);
            keys[row * 24 + ent + 1] =
                ((uint32_t)__half_as_ushort(__float2half_rn(v2)) << 16) | (p12 & 0xffff);
            keys[row * 24 + ent + 2] =
                ((uint32_t)__half_as_ushort(__float2half_rn(v3)) << 16) | (p3 & 0xffff);
        }
    __syncthreads();
    #pragma unroll
    for (int j = 0; j < 12; ++j) {
        int lin = tid + j * 256;                 // 0..3071
        g_cand[(size_t)mt * (128 * NCAND) + lin] = keys[lin];
    }
}

// ============================================================
// K3b: barrier-free warp-per-row rerank + gather.
// One warp owns one row end-to-end; winner is lane-uniform
// (butterfly-reduced dots), so no smem result or atomicMin.
// ============================================================
__global__ __launch_bounds__(256) void k_rerank(const float* __restrict__ X,
                                                const float* __restrict__ E,
                                                float* __restrict__ out) {
    __shared__ float lsum[8];
    const int tid = threadIdx.x;
    const int lane = tid & 31;
    const int wrp = tid >> 5;
    const int row = blockIdx.x * 8 + wrp;

    unsigned int key = (lane < NCAND) ? g_cand[(size_t)row * NCAND + lane] : 0xFFFFFFFFu;
    const unsigned int mkey = __reduce_min_sync(0xffffffffu, key);
    const float thresh = __half2float(__ushort_as_half((unsigned short)(mkey >> 16)))
                         + RERANK_THRESH;

    // X row resident in registers: 16 floats per lane
    float4 x[4];
    #pragma unroll
    for (int j = 0; j < 4; ++j)
        x[j] = *(const float4*)(X + (size_t)row * DIM + j * 128 + lane * 4);

    float bests = FLT_MAX;
    int   bestc = 0x7fffffff;
    #pragma unroll 1
    for (int c = 0; c < NCAND; ++c) {
        const unsigned int kc = __shfl_sync(0xffffffffu, key, c);
        const float v = __half2float(__ushort_as_half((unsigned short)(kc >> 16)));
        if (v <= thresh) {
            const int col = (int)(kc & 0xffffu);
            const float* er = E + (size_t)col * DIM;
            float dot = 0.0f;
            #pragma unroll
            for (int j = 0; j < 4; ++j) {
                float4 e = *(const float4*)(er + j * 128 + lane * 4);
                dot = fmaf(x[j].x, e.x, dot); dot = fmaf(x[j].y, e.y, dot);
                dot = fmaf(x[j].z, e.z, dot); dot = fmaf(x[j].w, e.w, dot);
            }
            #pragma unroll
            for (int o = 16; o; o >>= 1) dot += __shfl_xor_sync(0xffffffffu, dot, o);
            const float s = fmaf(-2.0f, dot, __ldg(&g_enorm2[col]));
            if (s < bests || (s == bests && col < bestc)) { bests = s; bestc = col; }
        }
    }

    // gather + dw + loss (bestc is lane-uniform)
    const float* er = E + (size_t)bestc * DIM;
    float* dwr = g_dw + (size_t)bestc * DIM;
    float ls = 0.0f;
    #pragma unroll
    for (int j = 0; j < 4; ++j) {
        const int d = j * 128 + lane * 4;
        float4 q = *(const float4*)(er + d);
        *(float4*)(out + O_Q + (size_t)row * DIM + d) = q;
        atomicAdd((float4*)(dwr + d), x[j]);
        float dx = q.x - x[j].x, dy = q.y - x[j].y;
        float dz = q.z - x[j].z, dw = q.w - x[j].w;
        ls += dx * dx + dy * dy + dz * dz + dw * dw;
    }
    #pragma unroll
    for (int o = 16; o; o >>= 1) ls += __shfl_xor_sync(0xffffffffu, ls, o);
    if (lane == 0) {
        lsum[wrp] = ls;
        atomicAdd(&g_counts[bestc], 1.0f);
    }
    __syncthreads();
    if (tid == 0) {
        float s = 0.0f;
        #pragma unroll
        for (int w = 0; w < 8; ++w) s += lsum[w];
        atomicAdd(&g_loss_sum, s);
    }
}

// ============================================================
// K5a: EMA cluster-size pre + global sums
// ============================================================
__global__ __launch_bounds__(256) void k_stats1(const float* __restrict__ cs_in) {
    __shared__ float sn[8], sp[8];
    int k = blockIdx.x * 256 + threadIdx.x;
    float cnt = g_counts[k];
    float pre = fmaf(cs_in[k], DECAYF, OMDF * cnt);
    g_cs_pre[k] = pre;
    float p = cnt * (1.0f / (float)NROWS);
    float pl = p * logf(p + 1e-10f);
    float ns = pre, ps = pl;
    #pragma unroll
    for (int o = 16; o; o >>= 1) {
        ns += __shfl_xor_sync(0xffffffffu, ns, o);
        ps += __shfl_xor_sync(0xffffffffu, ps, o);
    }
    int lane = threadIdx.x & 31, warp = threadIdx.x >> 5;
    if (lane == 0) { sn[warp] = ns; sp[warp] = ps; }
    __syncthreads();
    if (threadIdx.x == 0) {
        float a = 0.0f, b = 0.0f;
        #pragma unroll
        for (int w = 0; w < 8; ++w) { a += sn[w]; b += sp[w]; }
        atomicAdd(&g_n_sum, a);
        atomicAdd(&g_plogp_sum, b);
    }
}

// ============================================================
// K6: finalize: new_cs, loss, perplexity, new_w, new_embedding
// ============================================================
__global__ __launch_bounds__(256) void k_final(const float* __restrict__ ema_w,
                                               float* __restrict__ out) {
    const float n = g_n_sum;
    const float inv_den = 1.0f / (n + (float)KC * EPSF);
    if (blockIdx.x == 0 && threadIdx.x == 0) {
        out[O_LOSS] = 0.25f * (g_loss_sum / (float)(NROWS * DIM));
        out[O_PERP] = expf(-g_plogp_sum);
    }
    int i = blockIdx.x * blockDim.x + threadIdx.x;
    int total = KC * DIM / 4;
    int stride = gridDim.x * blockDim.x;
    for (; i < total; i += stride) {
        int e = i * 4;
        int k = e >> 9;
        float ncs = (g_cs_pre[k] + EPSF) * inv_den * n;
        if ((e & (DIM - 1)) == 0) out[O_CS + k] = ncs;
        float4 w  = *(const float4*)(ema_w + e);
        float4 dv = *(const float4*)(g_dw + e);
        float4 nw;
        nw.x = fmaf(w.x, DECAYF, OMDF * dv.x);
        nw.y = fmaf(w.y, DECAYF, OMDF * dv.y);
        nw.z = fmaf(w.z, DECAYF, OMDF * dv.z);
        nw.w = fmaf(w.w, DECAYF, OMDF * dv.w);
        *(float2*)(out + O_W + e)     = make_float2(nw.x, nw.y);
        *(float2*)(out + O_W + e + 2) = make_float2(nw.z, nw.w);
        float inv = 1.0f / ncs;
        *(float2*)(out + O_EMB + e)     = make_float2(nw.x * inv, nw.y * inv);
        *(float2*)(out + O_EMB + e + 2) = make_float2(nw.z * inv, nw.w * inv);
    }
}

// ============================================================
extern "C" void kernel_launch(void* const* d_in, const int* in_sizes, int n_in,
                              void* d_out, int out_size) {
    const float* X     = (const float*)d_in[0];
    const float* E     = (const float*)d_in[1];
    const float* cs    = (const float*)d_in[2];
    const float* ema_w = (const float*)d_in[3];
    float* out = (float*)d_out;

    cudaFuncSetAttribute(k_argmin_mma, cudaFuncAttributeMaxDynamicSharedMemorySize, SMEM_MMA);

    k_prep  <<<4096, 256>>>(X, E);
    k_argmin_mma<<<NROWS / 128, 256, SMEM_MMA>>>();
    k_rerank<<<NROWS / 8, 256>>>(X, E, out);
    k_stats1<<<KC / 256, 256>>>(cs);
    k_final <<<2048, 256>>>(ema_w, out);
}